// round 2
// baseline (speedup 1.0000x reference)
#include <cuda_runtime.h>
#include <math.h>

#define NBLK 128
#define TPB  256
#define B_   64
#define T_   256
#define V_   8000
#define E_   512
#define H_   1024
#define G4H  4096
#define TDEC 255
#define START_TOK 1

typedef unsigned long long u64;

// ---------------- packed f32x2 helpers (FFMA2: 2 MACs per issue) -------------------
__device__ __forceinline__ u64 pack2(float lo, float hi) {
    u64 r;
    asm("mov.b64 %0, {%1, %2};" : "=l"(r)
        : "r"(__float_as_uint(lo)), "r"(__float_as_uint(hi)));
    return r;
}
__device__ __forceinline__ float2 unpack2(u64 v) {
    unsigned lo, hi;
    asm("mov.b64 {%0, %1}, %2;" : "=r"(lo), "=r"(hi) : "l"(v));
    return make_float2(__uint_as_float(lo), __uint_as_float(hi));
}
__device__ __forceinline__ void fma2(u64& d, u64 a, u64 b) {
    asm("fma.rn.f32x2 %0, %1, %2, %0;" : "+l"(d) : "l"(a), "l"(b));
}

// ---------------- device scratch (allocation-free rule: __device__ globals) --------
__device__ float g_P_enc[(size_t)V_ * G4H];      // embed @ Wih^T + b (encoder)
__device__ float g_P_dec[(size_t)V_ * G4H];      // decoder table
__device__ float g_Hdec[(size_t)TDEC * B_ * H_]; // all decoder hidden states
__device__ float g_hbuf[2][B_ * H_];             // double-buffered h
__device__ unsigned g_arrive = 0;
__device__ unsigned g_phase  = 0;

// ---------------- NT SGEMM: C[M,N] = A[M,K] * B[N,K]^T + bias[N] -------------------
// MODE 0: plain row-major C.  MODE 1: logits remap, m = t*64+b -> C[(b*255+t)*N + n]
template<int MODE>
__global__ void __launch_bounds__(256) gemm_nt(
    const float* __restrict__ A, const float* __restrict__ Bm,
    const float* __restrict__ bias, float* __restrict__ C,
    int M, int N, int K)
{
    __shared__ u64   As2[16][132];   // duplicated-pair a values (a,a)
    __shared__ float Bs[16][132];
    const int tid = threadIdx.x;
    const int bm = blockIdx.y * 128;
    const int bn = blockIdx.x * 128;
    const int tx = tid & 15, ty = tid >> 4;

    u64 acc2[8][4];
#pragma unroll
    for (int i = 0; i < 8; i++)
#pragma unroll
        for (int j = 0; j < 4; j++) acc2[i][j] = 0ull;

    for (int kc = 0; kc < K; kc += 16) {
#pragma unroll
        for (int u = 0; u < 2; u++) {
            int i = tid + u * 256;            // 0..511
            int row = i >> 2;                 // 0..127
            int kcol = (i & 3) * 4;           // 0,4,8,12
            float4 va = make_float4(0, 0, 0, 0);
            float4 vb = make_float4(0, 0, 0, 0);
            int am = bm + row;
            if (am < M) va = *(const float4*)&A[(size_t)am * K + kc + kcol];
            int bnr = bn + row;
            if (bnr < N) vb = *(const float4*)&Bm[(size_t)bnr * K + kc + kcol];
            As2[kcol + 0][row] = pack2(va.x, va.x);
            As2[kcol + 1][row] = pack2(va.y, va.y);
            As2[kcol + 2][row] = pack2(va.z, va.z);
            As2[kcol + 3][row] = pack2(va.w, va.w);
            Bs[kcol + 0][row] = vb.x; Bs[kcol + 1][row] = vb.y;
            Bs[kcol + 2][row] = vb.z; Bs[kcol + 3][row] = vb.w;
        }
        __syncthreads();
#pragma unroll
        for (int kk = 0; kk < 16; kk++) {
            u64 a2[8], b2[4];
            const u64* ap = &As2[kk][ty * 8];
            const u64* bp = (const u64*)&Bs[kk][tx * 8];  // natural pairs (b0,b1)...
#pragma unroll
            for (int i = 0; i < 8; i++) a2[i] = ap[i];
#pragma unroll
            for (int p = 0; p < 4; p++) b2[p] = bp[p];
#pragma unroll
            for (int i = 0; i < 8; i++)
#pragma unroll
                for (int p = 0; p < 4; p++)
                    fma2(acc2[i][p], a2[i], b2[p]);
        }
        __syncthreads();
    }

#pragma unroll
    for (int i = 0; i < 8; i++) {
        int m = bm + ty * 8 + i;
        if (m >= M) continue;
        size_t outbase;
        if (MODE == 0) {
            outbase = (size_t)m * N;
        } else {
            int tstep = m >> 6;
            int bb = m & 63;
            outbase = ((size_t)bb * TDEC + tstep) * N;
        }
#pragma unroll
        for (int p = 0; p < 4; p++) {
            float2 v = unpack2(acc2[i][p]);
            int n = bn + tx * 8 + 2 * p;
            if (n < N)     C[outbase + n]     = v.x + bias[n];
            if (n + 1 < N) C[outbase + n + 1] = v.y + bias[n + 1];
        }
    }
}

// ---------------- persistent LSTM recurrence (encoder 256 + decoder 255 steps) -----
// 128 blocks * 256 threads; block owns j-slice [bid*8, bid*8+8) of H, all 64 batches.
__global__ void __launch_bounds__(TPB, 1) lstm_recurrence(
    const int* __restrict__ seqs,
    const float* __restrict__ Whh_e,
    const float* __restrict__ Whh_d)
{
    __shared__ u64   h_s2[32][34];     // h chunk, transposed batch-pairs: [k][bpair]
    __shared__ float w_s[32][33];      // 32 Whh rows x 32 k
    __shared__ float gate_s[32][65];   // gate values [row][b]
    __shared__ float c_s[8][64];       // persistent cell state [jj][b]
    __shared__ int   tok_s[64];

    const int tid = threadIdx.x;
    const int bid = blockIdx.x;

    unsigned base = 0;
    if (tid == 0) base = atomicAdd(&g_phase, 0u);   // phase baseline (replay-safe)
    unsigned tgt = 0;

    for (int i = bid * TPB + tid; i < B_ * H_; i += NBLK * TPB) g_hbuf[0][i] = 0.f;
#pragma unroll
    for (int u = 0; u < 2; u++) {
        int p = tid + u * TPB;
        c_s[p >> 6][p & 63] = 0.f;
    }

#define GSYNC() do {                                                     \
    __syncthreads();                                                     \
    if (tid == 0) {                                                      \
        ++tgt;                                                           \
        __threadfence();                                                 \
        unsigned old_ = atomicAdd(&g_arrive, 1u);                        \
        if (old_ == NBLK - 1) {                                          \
            atomicExch(&g_arrive, 0u);                                   \
            __threadfence();                                             \
            atomicAdd(&g_phase, 1u);                                     \
        } else {                                                         \
            while ((unsigned)(atomicAdd(&g_phase, 0u) - base) < tgt)     \
                __nanosleep(64);                                         \
            __threadfence();                                             \
        }                                                                \
    }                                                                    \
    __syncthreads();                                                     \
} while (0)

    GSYNC();   // h0 visible everywhere

    const int rr  = tid >> 3;            // 0..31: which of my 32 gate rows
    const int b0  = (tid & 7) << 3;      // batch group 0,8,...,56
    const int bp0 = (tid & 7) << 2;      // batch-pair group 0,4,...,28
    const int g   = rr >> 3;             // gate index 0..3 (i,f,g,o)
    const int jj  = rr & 7;
    const int row = g * H_ + bid * 8 + jj;   // Whh row / gate column

    for (int s = 0; s < T_ + TDEC; s++) {
        const bool enc = (s < T_);
        const int t = enc ? s : s - T_;
        const float* __restrict__ W = enc ? Whh_e : Whh_d;
        const float* __restrict__ P = enc ? g_P_enc : g_P_dec;
        const float* __restrict__ hprev = g_hbuf[s & 1];

        if (tid < B_) {
            tok_s[tid] = enc ? seqs[tid * T_ + t]
                             : (t == 0 ? START_TOK : seqs[tid * T_ + t]);
        }

        u64 acc2[4];
#pragma unroll
        for (int u = 0; u < 4; u++) acc2[u] = 0ull;

        for (int kc = 0; kc < H_; kc += 32) {
#pragma unroll
            for (int u = 0; u < 4; u++) {        // pack h chunk: pairs of batches
                int i = tid + u * TPB;           // 0..1023
                int bp = i >> 5, kk = i & 31;    // coalesced k-reads per batch row
                float lo = hprev[(2 * bp) * H_ + kc + kk];
                float hi = hprev[(2 * bp + 1) * H_ + kc + kk];
                h_s2[kk][bp] = pack2(lo, hi);
            }
#pragma unroll
            for (int u = 0; u < 4; u++) {        // load 32 Whh rows x 32 k
                int i = tid + u * TPB;
                int rw = i >> 5, kk = i & 31;
                int grow = (rw >> 3) * H_ + bid * 8 + (rw & 7);
                w_s[rw][kk] = W[(size_t)grow * H_ + kc + kk];
            }
            __syncthreads();
#pragma unroll
            for (int kk = 0; kk < 32; kk++) {
                float w = w_s[rr][kk];
                u64 wp = pack2(w, w);
                const u64* hp = &h_s2[kk][bp0];
                fma2(acc2[0], wp, hp[0]);
                fma2(acc2[1], wp, hp[1]);
                fma2(acc2[2], wp, hp[2]);
                fma2(acc2[3], wp, hp[3]);
            }
            __syncthreads();
        }

        // add precomputed input projection (+bias folded in) and stage gates
#pragma unroll
        for (int u = 0; u < 4; u++) {
            float2 v = unpack2(acc2[u]);
            int bA = b0 + 2 * u, bB = b0 + 2 * u + 1;
            gate_s[rr][bA] = v.x + __ldg(&P[(size_t)tok_s[bA] * G4H + row]);
            gate_s[rr][bB] = v.y + __ldg(&P[(size_t)tok_s[bB] * G4H + row]);
        }
        __syncthreads();

        // elementwise LSTM update: 512 (b,j) cells, 2 per thread
#pragma unroll
        for (int u = 0; u < 2; u++) {
            int p = tid + u * TPB;
            int jp = p >> 6, bb = p & 63;
            float gi = gate_s[jp][bb];
            float gf = gate_s[8 + jp][bb];
            float gg = gate_s[16 + jp][bb];
            float go = gate_s[24 + jp][bb];
            float c = c_s[jp][bb];
            float si = 1.f / (1.f + expf(-gi));
            float sf = 1.f / (1.f + expf(-gf));
            float so = 1.f / (1.f + expf(-go));
            float cn = sf * c + si * tanhf(gg);
            float hn = so * tanhf(cn);
            c_s[jp][bb] = cn;
            int jg = bid * 8 + jp;
            g_hbuf[(s + 1) & 1][bb * H_ + jg] = hn;
            if (!enc) g_Hdec[((size_t)t * B_ + bb) * H_ + jg] = hn;
        }
        GSYNC();
    }
#undef GSYNC
}

// ---------------- launch ------------------------------------------------------------
extern "C" void kernel_launch(void* const* d_in, const int* in_sizes, int n_in,
                              void* d_out, int out_size)
{
    (void)in_sizes; (void)n_in; (void)out_size;
    const int*   seqs    = (const int*)  d_in[1];
    const float* enc_emb = (const float*)d_in[2];
    const float* enc_Wih = (const float*)d_in[3];
    const float* enc_Whh = (const float*)d_in[4];
    const float* enc_b   = (const float*)d_in[5];
    const float* dec_emb = (const float*)d_in[6];
    const float* dec_Wih = (const float*)d_in[7];
    const float* dec_Whh = (const float*)d_in[8];
    const float* dec_b   = (const float*)d_in[9];
    const float* out_W   = (const float*)d_in[10];
    const float* out_b   = (const float*)d_in[11];
    float* out = (float*)d_out;

    float *Penc, *Pdec, *Hdec;
    cudaGetSymbolAddress((void**)&Penc, g_P_enc);
    cudaGetSymbolAddress((void**)&Pdec, g_P_dec);
    cudaGetSymbolAddress((void**)&Hdec, g_Hdec);

    // vocab projection tables: P = embed @ Wih^T + b   [V, 4H]
    dim3 gP(G4H / 128, (V_ + 127) / 128);
    gemm_nt<0><<<gP, 256>>>(enc_emb, enc_Wih, enc_b, Penc, V_, G4H, E_);
    gemm_nt<0><<<gP, 256>>>(dec_emb, dec_Wih, dec_b, Pdec, V_, G4H, E_);

    // serial encoder + decoder recurrence (persistent kernel)
    lstm_recurrence<<<NBLK, TPB>>>(seqs, enc_Whh, dec_Whh);

    // batched output projection: logits = Hdec @ out_W^T + out_b, remapped to [B,255,V]
    dim3 gL((V_ + 127) / 128, (TDEC * B_ + 127) / 128);
    gemm_nt<1><<<gL, 256>>>(Hdec, out_W, out_b, out, TDEC * B_, V_, H_);
}

// round 3
// speedup vs baseline: 1.0014x; 1.0014x over previous
#include <cuda_runtime.h>
#include <math.h>

#define NBLK 128
#define TPB  256
#define B_   64
#define T_   256
#define V_   8000
#define E_   512
#define H_   1024
#define G4H  4096
#define TDEC 255
#define START_TOK 1

typedef unsigned long long u64;

// ---------------- packed f32x2 helpers (FFMA2: 2 MACs per issue) -------------------
__device__ __forceinline__ u64 pack2(float lo, float hi) {
    u64 r;
    asm("mov.b64 %0, {%1, %2};" : "=l"(r)
        : "r"(__float_as_uint(lo)), "r"(__float_as_uint(hi)));
    return r;
}
__device__ __forceinline__ float2 unpack2(u64 v) {
    unsigned lo, hi;
    asm("mov.b64 {%0, %1}, %2;" : "=r"(lo), "=r"(hi) : "l"(v));
    return make_float2(__uint_as_float(lo), __uint_as_float(hi));
}
__device__ __forceinline__ void fma2(u64& d, u64 a, u64 b) {
    asm("fma.rn.f32x2 %0, %1, %2, %0;" : "+l"(d) : "l"(a), "l"(b));
}

// ---------------- device scratch (allocation-free rule: __device__ globals) --------
__device__ float g_P_enc[(size_t)V_ * G4H];      // embed @ Wih^T + b (encoder)
__device__ float g_P_dec[(size_t)V_ * G4H];      // decoder table
__device__ float g_Hdec[(size_t)TDEC * B_ * H_]; // all decoder hidden states
__device__ float g_hbuf[2][B_ * H_];             // double-buffered h
__device__ unsigned g_arrive = 0;
__device__ unsigned g_phase  = 0;

// ---------------- NT SGEMM: C[M,N] = A[M,K] * B[N,K]^T + bias[N] -------------------
// MODE 0: plain row-major C.  MODE 1: logits remap, m = t*64+b -> C[(b*255+t)*N + n]
template<int MODE>
__global__ void __launch_bounds__(256) gemm_nt(
    const float* __restrict__ A, const float* __restrict__ Bm,
    const float* __restrict__ bias, float* __restrict__ C,
    int M, int N, int K)
{
    __shared__ u64   As2[16][132];   // duplicated-pair a values (a,a)
    __shared__ float Bs[16][132];
    const int tid = threadIdx.x;
    const int bm = blockIdx.y * 128;
    const int bn = blockIdx.x * 128;
    const int tx = tid & 15, ty = tid >> 4;

    u64 acc2[8][4];
#pragma unroll
    for (int i = 0; i < 8; i++)
#pragma unroll
        for (int j = 0; j < 4; j++) acc2[i][j] = 0ull;

    for (int kc = 0; kc < K; kc += 16) {
#pragma unroll
        for (int u = 0; u < 2; u++) {
            int i = tid + u * 256;            // 0..511
            int row = i >> 2;                 // 0..127
            int kcol = (i & 3) * 4;           // 0,4,8,12
            float4 va = make_float4(0, 0, 0, 0);
            float4 vb = make_float4(0, 0, 0, 0);
            int am = bm + row;
            if (am < M) va = *(const float4*)&A[(size_t)am * K + kc + kcol];
            int bnr = bn + row;
            if (bnr < N) vb = *(const float4*)&Bm[(size_t)bnr * K + kc + kcol];
            As2[kcol + 0][row] = pack2(va.x, va.x);
            As2[kcol + 1][row] = pack2(va.y, va.y);
            As2[kcol + 2][row] = pack2(va.z, va.z);
            As2[kcol + 3][row] = pack2(va.w, va.w);
            Bs[kcol + 0][row] = vb.x; Bs[kcol + 1][row] = vb.y;
            Bs[kcol + 2][row] = vb.z; Bs[kcol + 3][row] = vb.w;
        }
        __syncthreads();
#pragma unroll
        for (int kk = 0; kk < 16; kk++) {
            u64 a2[8], b2[4];
            const u64* ap = &As2[kk][ty * 8];
            const u64* bp = (const u64*)&Bs[kk][tx * 8];  // natural pairs (b0,b1)...
#pragma unroll
            for (int i = 0; i < 8; i++) a2[i] = ap[i];
#pragma unroll
            for (int p = 0; p < 4; p++) b2[p] = bp[p];
#pragma unroll
            for (int i = 0; i < 8; i++)
#pragma unroll
                for (int p = 0; p < 4; p++)
                    fma2(acc2[i][p], a2[i], b2[p]);
        }
        __syncthreads();
    }

#pragma unroll
    for (int i = 0; i < 8; i++) {
        int m = bm + ty * 8 + i;
        if (m >= M) continue;
        size_t outbase;
        if (MODE == 0) {
            outbase = (size_t)m * N;
        } else {
            int tstep = m >> 6;
            int bb = m & 63;
            outbase = ((size_t)bb * TDEC + tstep) * N;
        }
#pragma unroll
        for (int p = 0; p < 4; p++) {
            float2 v = unpack2(acc2[i][p]);
            int n = bn + tx * 8 + 2 * p;
            if (n < N)     C[outbase + n]     = v.x + bias[n];
            if (n + 1 < N) C[outbase + n + 1] = v.y + bias[n + 1];
        }
    }
}

// ---------------- persistent LSTM recurrence (encoder 256 + decoder 255 steps) -----
// 128 blocks * 256 threads; block owns j-slice [bid*8, bid*8+8) of H, all 64 batches.
__global__ void __launch_bounds__(TPB, 1) lstm_recurrence(
    const int* __restrict__ seqs,
    const float* __restrict__ Whh_e,
    const float* __restrict__ Whh_d)
{
    __shared__ u64   h_s2[32][34];     // h chunk, transposed batch-pairs: [k][bpair]
    __shared__ float w_s[32][33];      // 32 Whh rows x 32 k
    __shared__ float gate_s[32][65];   // gate values [row][b]
    __shared__ float c_s[8][64];       // persistent cell state [jj][b]
    __shared__ int   tok_s[64];

    const int tid = threadIdx.x;
    const int bid = blockIdx.x;

    unsigned base = 0;
    if (tid == 0) base = atomicAdd(&g_phase, 0u);   // phase baseline (replay-safe)
    unsigned tgt = 0;

    for (int i = bid * TPB + tid; i < B_ * H_; i += NBLK * TPB) g_hbuf[0][i] = 0.f;
#pragma unroll
    for (int u = 0; u < 2; u++) {
        int p = tid + u * TPB;
        c_s[p >> 6][p & 63] = 0.f;
    }

#define GSYNC() do {                                                     \
    __syncthreads();                                                     \
    if (tid == 0) {                                                      \
        ++tgt;                                                           \
        __threadfence();                                                 \
        unsigned old_ = atomicAdd(&g_arrive, 1u);                        \
        if (old_ == NBLK - 1) {                                          \
            atomicExch(&g_arrive, 0u);                                   \
            __threadfence();                                             \
            atomicAdd(&g_phase, 1u);                                     \
        } else {                                                         \
            while ((unsigned)(atomicAdd(&g_phase, 0u) - base) < tgt)     \
                __nanosleep(64);                                         \
            __threadfence();                                             \
        }                                                                \
    }                                                                    \
    __syncthreads();                                                     \
} while (0)

    GSYNC();   // h0 visible everywhere

    const int rr  = tid >> 3;            // 0..31: which of my 32 gate rows
    const int b0  = (tid & 7) << 3;      // batch group 0,8,...,56
    const int bp0 = (tid & 7) << 2;      // batch-pair group 0,4,...,28
    const int g   = rr >> 3;             // gate index 0..3 (i,f,g,o)
    const int jj  = rr & 7;
    const int row = g * H_ + bid * 8 + jj;   // Whh row / gate column

    for (int s = 0; s < T_ + TDEC; s++) {
        const bool enc = (s < T_);
        const int t = enc ? s : s - T_;
        const float* __restrict__ W = enc ? Whh_e : Whh_d;
        const float* __restrict__ P = enc ? g_P_enc : g_P_dec;
        const float* __restrict__ hprev = g_hbuf[s & 1];

        if (tid < B_) {
            tok_s[tid] = enc ? seqs[tid * T_ + t]
                             : (t == 0 ? START_TOK : seqs[tid * T_ + t]);
        }

        u64 acc2[4];
#pragma unroll
        for (int u = 0; u < 4; u++) acc2[u] = 0ull;

        for (int kc = 0; kc < H_; kc += 32) {
#pragma unroll
            for (int u = 0; u < 4; u++) {        // pack h chunk: pairs of batches
                int i = tid + u * TPB;           // 0..1023
                int bp = i >> 5, kk = i & 31;    // coalesced k-reads per batch row
                float lo = hprev[(2 * bp) * H_ + kc + kk];
                float hi = hprev[(2 * bp + 1) * H_ + kc + kk];
                h_s2[kk][bp] = pack2(lo, hi);
            }
#pragma unroll
            for (int u = 0; u < 4; u++) {        // load 32 Whh rows x 32 k
                int i = tid + u * TPB;
                int rw = i >> 5, kk = i & 31;
                int grow = (rw >> 3) * H_ + bid * 8 + (rw & 7);
                w_s[rw][kk] = W[(size_t)grow * H_ + kc + kk];
            }
            __syncthreads();
#pragma unroll
            for (int kk = 0; kk < 32; kk++) {
                float w = w_s[rr][kk];
                u64 wp = pack2(w, w);
                const u64* hp = &h_s2[kk][bp0];
                fma2(acc2[0], wp, hp[0]);
                fma2(acc2[1], wp, hp[1]);
                fma2(acc2[2], wp, hp[2]);
                fma2(acc2[3], wp, hp[3]);
            }
            __syncthreads();
        }

        // add precomputed input projection (+bias folded in) and stage gates
#pragma unroll
        for (int u = 0; u < 4; u++) {
            float2 v = unpack2(acc2[u]);
            int bA = b0 + 2 * u, bB = b0 + 2 * u + 1;
            gate_s[rr][bA] = v.x + __ldg(&P[(size_t)tok_s[bA] * G4H + row]);
            gate_s[rr][bB] = v.y + __ldg(&P[(size_t)tok_s[bB] * G4H + row]);
        }
        __syncthreads();

        // elementwise LSTM update: 512 (b,j) cells, 2 per thread
#pragma unroll
        for (int u = 0; u < 2; u++) {
            int p = tid + u * TPB;
            int jp = p >> 6, bb = p & 63;
            float gi = gate_s[jp][bb];
            float gf = gate_s[8 + jp][bb];
            float gg = gate_s[16 + jp][bb];
            float go = gate_s[24 + jp][bb];
            float c = c_s[jp][bb];
            float si = 1.f / (1.f + expf(-gi));
            float sf = 1.f / (1.f + expf(-gf));
            float so = 1.f / (1.f + expf(-go));
            float cn = sf * c + si * tanhf(gg);
            float hn = so * tanhf(cn);
            c_s[jp][bb] = cn;
            int jg = bid * 8 + jp;
            g_hbuf[(s + 1) & 1][bb * H_ + jg] = hn;
            if (!enc) g_Hdec[((size_t)t * B_ + bb) * H_ + jg] = hn;
        }
        GSYNC();
    }
#undef GSYNC
}

// ---------------- launch ------------------------------------------------------------
extern "C" void kernel_launch(void* const* d_in, const int* in_sizes, int n_in,
                              void* d_out, int out_size)
{
    (void)in_sizes; (void)n_in; (void)out_size;
    const int*   seqs    = (const int*)  d_in[1];
    const float* enc_emb = (const float*)d_in[2];
    const float* enc_Wih = (const float*)d_in[3];
    const float* enc_Whh = (const float*)d_in[4];
    const float* enc_b   = (const float*)d_in[5];
    const float* dec_emb = (const float*)d_in[6];
    const float* dec_Wih = (const float*)d_in[7];
    const float* dec_Whh = (const float*)d_in[8];
    const float* dec_b   = (const float*)d_in[9];
    const float* out_W   = (const float*)d_in[10];
    const float* out_b   = (const float*)d_in[11];
    float* out = (float*)d_out;

    float *Penc, *Pdec, *Hdec;
    cudaGetSymbolAddress((void**)&Penc, g_P_enc);
    cudaGetSymbolAddress((void**)&Pdec, g_P_dec);
    cudaGetSymbolAddress((void**)&Hdec, g_Hdec);

    // vocab projection tables: P = embed @ Wih^T + b   [V, 4H]
    dim3 gP(G4H / 128, (V_ + 127) / 128);
    gemm_nt<0><<<gP, 256>>>(enc_emb, enc_Wih, enc_b, Penc, V_, G4H, E_);
    gemm_nt<0><<<gP, 256>>>(dec_emb, dec_Wih, dec_b, Pdec, V_, G4H, E_);

    // serial encoder + decoder recurrence (persistent kernel)
    lstm_recurrence<<<NBLK, TPB>>>(seqs, enc_Whh, dec_Whh);

    // batched output projection: logits = Hdec @ out_W^T + out_b, remapped to [B,255,V]
    dim3 gL((V_ + 127) / 128, (TDEC * B_ + 127) / 128);
    gemm_nt<1><<<gL, 256>>>(Hdec, out_W, out_b, out, TDEC * B_, V_, H_);
}

// round 9
// speedup vs baseline: 4.2662x; 4.2604x over previous
#include <cuda_runtime.h>
#include <cuda_bf16.h>
#include <math.h>
#include <stdint.h>

#define NBLK 128
#define B_   64
#define T_   256
#define V_   8000
#define E_   512
#define H_   1024
#define G4H  4096
#define TDEC 255
#define START_TOK 1

#define MPAD_LOGITS 16384
#define NPAD_LOGITS 8192
#define MPAD_TAB    8064
#define K2_LOGITS   3072
#define K2_TAB      1536

#define GEMM_SMEM   131072          // 4 stages x (16KB A + 16KB B)
// recurrence smem: W 196608 | h 4x8192 (gates alias) | c 2048 | tok 256
#define RW_OFF      0
#define RH_OFF      196608
#define RC_OFF      229376
#define RT_OFF      231424
#define REC_SMEM    231680

// ---------------- PTX helpers -------------------------------------------------------
__device__ __forceinline__ uint32_t smem_u32(const void* p) {
    uint32_t a;
    asm("{ .reg .u64 t; cvta.to.shared.u64 t, %1; cvt.u32.u64 %0, t; }" : "=r"(a) : "l"(p));
    return a;
}
__device__ __forceinline__ uint32_t sw128(uint32_t off) {
    return off ^ ((off >> 3) & 0x70);
}
__device__ __forceinline__ void cp_async16(uint32_t dst, const void* src) {
    asm volatile("cp.async.cg.shared.global [%0], [%1], 16;" :: "r"(dst), "l"(src) : "memory");
}
#define CP_COMMIT() asm volatile("cp.async.commit_group;" ::: "memory")
template<int N> __device__ __forceinline__ void cp_wait() {
    asm volatile("cp.async.wait_group %0;" :: "n"(N) : "memory");
}
__device__ __forceinline__ void ldsm_x4(uint32_t r[4], uint32_t addr) {
    asm volatile("ldmatrix.sync.aligned.m8n8.x4.shared.b16 {%0,%1,%2,%3}, [%4];"
                 : "=r"(r[0]), "=r"(r[1]), "=r"(r[2]), "=r"(r[3]) : "r"(addr));
}
__device__ __forceinline__ void mma_bf16(float d[4], const uint32_t a[4],
                                         uint32_t b0, uint32_t b1) {
    asm volatile(
        "mma.sync.aligned.m16n8k16.row.col.f32.bf16.bf16.f32 "
        "{%0,%1,%2,%3}, {%4,%5,%6,%7}, {%8,%9}, {%0,%1,%2,%3};"
        : "+f"(d[0]), "+f"(d[1]), "+f"(d[2]), "+f"(d[3])
        : "r"(a[0]), "r"(a[1]), "r"(a[2]), "r"(a[3]), "r"(b0), "r"(b1));
}

// ---------------- device scratch ----------------------------------------------------
__device__ float g_P_enc[(size_t)V_ * G4H];
__device__ float g_P_dec[(size_t)V_ * G4H];
__device__ __nv_bfloat16 g_A2[(size_t)MPAD_LOGITS * K2_LOGITS];
__device__ __nv_bfloat16 g_B2[(size_t)NPAD_LOGITS * K2_LOGITS];
__device__ __nv_bfloat16 g_Wr_e[(size_t)G4H * K2_LOGITS];
__device__ __nv_bfloat16 g_Wr_d[(size_t)G4H * K2_LOGITS];
__device__ __nv_bfloat16 g_hhi[2][B_ * H_];
__device__ __nv_bfloat16 g_hlo[2][B_ * H_];
__device__ float g_bias_r[G4H];
__device__ unsigned g_arrive = 0;
__device__ unsigned g_phase  = 0;

// ---------------- split / reorder / zero helpers -----------------------------------
// MODEA=1: [hi|lo|hi] (A side).  MODEA=0: [hi|hi|lo] (B side).
// REORD=1: row m' -> orig row g*H + blk*8 + jj  (blk=m'>>5, g=(m'>>3)&3, jj=m'&7)
template<int MODEA, int REORD>
__global__ void split_rows(const float* __restrict__ X, __nv_bfloat16* __restrict__ Y,
                           int M_in, int M_pad, int K)
{
    int idx = blockIdx.x * blockDim.x + threadIdx.x;
    if (idx >= M_pad * K) return;
    int m = idx / K, k = idx - m * K;
    int src = m;
    if (REORD) {
        int blk = m >> 5, r = m & 31;
        src = (r >> 3) * H_ + blk * 8 + (r & 7);
    }
    float x = (src < M_in) ? X[(size_t)src * K + k] : 0.f;
    __nv_bfloat16 hi = __float2bfloat16(x);
    __nv_bfloat16 lo = __float2bfloat16(x - __bfloat162float(hi));
    size_t rb = (size_t)m * (3 * K);
    Y[rb + k]         = hi;
    Y[rb + K + k]     = MODEA ? lo : hi;
    Y[rb + 2 * K + k] = MODEA ? hi : lo;
}

__global__ void reorder_bias(const float* __restrict__ b, float* __restrict__ br) {
    int m = blockIdx.x * blockDim.x + threadIdx.x;
    if (m >= G4H) return;
    int blk = m >> 5, r = m & 31;
    br[m] = b[(r >> 3) * H_ + blk * 8 + (r & 7)];
}

__global__ void zero_buf(float4* p, size_t n16) {
    size_t i = (size_t)blockIdx.x * blockDim.x + threadIdx.x;
    if (i < n16) p[i] = make_float4(0.f, 0.f, 0.f, 0.f);
}

// ---------------- HMMA GEMM: C[M,N] = A2[M,K2] @ B2[N,K2]^T + bias ------------------
// Tiles 128x128, BK=64 bf16 (128B rows, sw128), 4-stage cp.async, 8 warps (4M x 2N).
// MODE 0: row-major C.  MODE 1: logits remap m=t*64+b -> C[(b*255+t)*ldC + n]
template<int MODE>
__global__ void __launch_bounds__(256) mma_nt(
    const __nv_bfloat16* __restrict__ A2, const __nv_bfloat16* __restrict__ B2,
    const float* __restrict__ bias, float* __restrict__ C,
    int M_eff, int N_eff, int K2, int ldC)
{
    extern __shared__ __align__(1024) char dsm[];
    const uint32_t sb = smem_u32(dsm);
    const int tid = threadIdx.x;
    const int wid = tid >> 5, lid = tid & 31;
    const int wm = wid & 3, wn = wid >> 2;
    const int bm = blockIdx.y * 128, bn = blockIdx.x * 128;
    const int nch = K2 / 64;

    auto loadT = [&](int c) {
        int st = c & 3;
#pragma unroll
        for (int j = 0; j < 4; j++) {
            int i = tid + j * 256;
            int r = i >> 3, cb = (i & 7) * 16;
            cp_async16(sb + st * 16384 + sw128((uint32_t)(r * 128 + cb)),
                       (const char*)A2 + ((size_t)(bm + r) * K2 + c * 64) * 2 + cb);
        }
#pragma unroll
        for (int j = 0; j < 4; j++) {
            int i = tid + j * 256;
            int r = i >> 3, cb = (i & 7) * 16;
            cp_async16(sb + 65536 + st * 16384 + sw128((uint32_t)(r * 128 + cb)),
                       (const char*)B2 + ((size_t)(bn + r) * K2 + c * 64) * 2 + cb);
        }
        CP_COMMIT();
    };

    float acc[2][8][4];
#pragma unroll
    for (int i = 0; i < 2; i++)
#pragma unroll
        for (int j = 0; j < 8; j++)
#pragma unroll
            for (int q = 0; q < 4; q++) acc[i][j][q] = 0.f;

    loadT(0); loadT(1);
    for (int i = 0; i < nch; i++) {
        if (i + 2 < nch) { loadT(i + 2); cp_wait<2>(); }
        else             { cp_wait<0>(); }
        __syncthreads();
        const uint32_t ab = sb + (i & 3) * 16384;
        const uint32_t bb = sb + 65536 + (i & 3) * 16384;
#pragma unroll
        for (int ks = 0; ks < 4; ks++) {
            const uint32_t kb = (uint32_t)((ks * 16 + ((lid >> 4) << 3)) * 2);
            uint32_t a[2][4], b[4][4];
#pragma unroll
            for (int mi = 0; mi < 2; mi++)
                ldsm_x4(a[mi], ab + sw128((uint32_t)((wm * 32 + mi * 16 + (lid & 15)) * 128) + kb));
#pragma unroll
            for (int ni = 0; ni < 4; ni++)
                ldsm_x4(b[ni], bb + sw128((uint32_t)((wn * 64 + ni * 16 + (lid & 15)) * 128) + kb));
#pragma unroll
            for (int mi = 0; mi < 2; mi++)
#pragma unroll
                for (int ni = 0; ni < 4; ni++) {
                    mma_bf16(acc[mi][2 * ni + 0], a[mi], b[ni][0], b[ni][2]);
                    mma_bf16(acc[mi][2 * ni + 1], a[mi], b[ni][1], b[ni][3]);
                }
        }
        __syncthreads();
    }

#pragma unroll
    for (int mi = 0; mi < 2; mi++) {
        int m0 = bm + wm * 32 + mi * 16 + (lid >> 2);
#pragma unroll
        for (int half = 0; half < 2; half++) {
            int m = m0 + half * 8;
            if (m >= M_eff) continue;
            size_t obase;
            if (MODE == 0) obase = (size_t)m * ldC;
            else {
                int t = m >> 6, b = m & 63;
                obase = ((size_t)b * TDEC + t) * ldC;
            }
#pragma unroll
            for (int nj = 0; nj < 8; nj++) {
                int n = bn + wn * 64 + nj * 8 + (lid & 3) * 2;
                float v0 = acc[mi][nj][half * 2 + 0];
                float v1 = acc[mi][nj][half * 2 + 1];
                if (n < N_eff)     C[obase + n]     = v0 + __ldg(&bias[n]);
                if (n + 1 < N_eff) C[obase + n + 1] = v1 + __ldg(&bias[n + 1]);
            }
        }
    }
}

// ---------------- persistent HMMA LSTM recurrence ----------------------------------
// 128 blocks x 256 thr. Block owns 32 REORDERED gate rows = all 4 gates of hidden
// units j in [bid*8, bid*8+8). W' slice (32 x 3072 bf16, sw128) resident in smem.
// Per step: gates[64x32] = h_split[64x3072] @ W'^T; elementwise local; h re-split.
__global__ void __launch_bounds__(256, 1) lstm_rec_mma(
    const int* __restrict__ seqs,
    const __nv_bfloat16* __restrict__ Wr_e,
    const __nv_bfloat16* __restrict__ Wr_d,
    __nv_bfloat16* __restrict__ A2out)
{
    extern __shared__ __align__(1024) char dsm[];
    const uint32_t sb = smem_u32(dsm);
    float* gate_s = (float*)(dsm + RH_OFF);      // [64][33] — aliases h ring
    float* c_s    = (float*)(dsm + RC_OFF);      // [512]: p = jj*64 + b
    int*   tok_s  = (int*)  (dsm + RT_OFF);

    const int tid = threadIdx.x;
    const int bid = blockIdx.x;
    const int wid = tid >> 5, lid = tid & 31;
    const int wm = wid & 3, wn = wid >> 2;

    unsigned base = 0;
    if (tid == 0) base = atomicAdd(&g_phase, 0u);
    unsigned tgt = 0;

    // zero h(0) buffers and cell state
    for (int i = bid * 256 + tid; i < B_ * H_; i += NBLK * 256) {
        g_hhi[0][i] = __float2bfloat16(0.f);
        g_hlo[0][i] = __float2bfloat16(0.f);
    }
    c_s[tid] = 0.f; c_s[tid + 256] = 0.f;

    auto loadW = [&](const __nv_bfloat16* Wsrc) {
#pragma unroll 4
        for (int j = 0; j < 48; j++) {
            int i = tid + j * 256;            // 0..12287
            int row = i / 384, cb = (i % 384) * 16;
            int c = cb >> 7, inner = cb & 127;
            cp_async16(sb + RW_OFF + c * 4096 + sw128((uint32_t)(row * 128 + inner)),
                       (const char*)Wsrc + (size_t)(bid * 32 + row) * 6144 + cb);
        }
        CP_COMMIT();
    };
    loadW(Wr_e);   // completion absorbed by first chunk-loop wait

#define GSYNC() do {                                                     \
    __syncthreads();                                                     \
    if (tid == 0) {                                                      \
        ++tgt;                                                           \
        __threadfence();                                                 \
        unsigned old_ = atomicAdd(&g_arrive, 1u);                        \
        if (old_ == NBLK - 1) {                                          \
            atomicExch(&g_arrive, 0u);                                   \
            __threadfence();                                             \
            atomicAdd(&g_phase, 1u);                                     \
        } else {                                                         \
            while ((unsigned)(atomicAdd(&g_phase, 0u) - base) < tgt)     \
                __nanosleep(64);                                         \
            __threadfence();                                             \
        }                                                                \
    }                                                                    \
    __syncthreads();                                                     \
} while (0)

    GSYNC();   // h0 visible everywhere

    for (int s = 0; s < T_ + TDEC; s++) {
        const bool enc = (s < T_);
        const int t = enc ? s : s - T_;
        const float* __restrict__ P = enc ? g_P_enc : g_P_dec;
        const __nv_bfloat16* __restrict__ hhi = g_hhi[s & 1];
        const __nv_bfloat16* __restrict__ hlo = g_hlo[s & 1];

        if (s == T_) loadW(Wr_d);            // decoder weights (drained by wait below)
        if (tid < B_)
            tok_s[tid] = enc ? seqs[tid * T_ + t]
                             : (t == 0 ? START_TOK : seqs[tid * T_ + t]);

        auto loadH = [&](int c) {
            const __nv_bfloat16* src = ((c >> 4) == 1) ? hlo : hhi;
            int j0 = (c & 15) * 64;
#pragma unroll
            for (int j = 0; j < 2; j++) {
                int i = tid + j * 256;
                int r = i >> 3, cb = (i & 7) * 16;
                cp_async16(sb + RH_OFF + (c & 3) * 8192 + sw128((uint32_t)(r * 128 + cb)),
                           (const char*)src + (size_t)r * 2048 + j0 * 2 + cb);
            }
            CP_COMMIT();
        };

        float accL[4] = {0.f, 0.f, 0.f, 0.f};
        float accH[4] = {0.f, 0.f, 0.f, 0.f};
        loadH(0); loadH(1);

        for (int i = 0; i < 48; i++) {
            if (i + 2 < 48) { loadH(i + 2); cp_wait<2>(); }
            else            { cp_wait<0>(); }
            __syncthreads();
            const uint32_t hb = sb + RH_OFF + (i & 3) * 8192;
            const uint32_t wb = sb + RW_OFF + i * 4096;
#pragma unroll
            for (int ks = 0; ks < 4; ks++) {
                const uint32_t kb = (uint32_t)((ks * 16 + ((lid >> 4) << 3)) * 2);
                uint32_t a[4], b[4];
                ldsm_x4(a, hb + sw128((uint32_t)((wm * 16 + (lid & 15)) * 128) + kb));
                ldsm_x4(b, wb + sw128((uint32_t)((wn * 16 + (lid & 15)) * 128) + kb));
                mma_bf16(accL, a, b[0], b[2]);
                mma_bf16(accH, a, b[1], b[3]);
            }
            __syncthreads();
        }

        {
            int r0 = wm * 16 + (lid >> 2);
            int c0 = wn * 16 + (lid & 3) * 2;
            gate_s[r0 * 33 + c0]           = accL[0];
            gate_s[r0 * 33 + c0 + 1]       = accL[1];
            gate_s[(r0 + 8) * 33 + c0]     = accL[2];
            gate_s[(r0 + 8) * 33 + c0 + 1] = accL[3];
            gate_s[r0 * 33 + c0 + 8]       = accH[0];
            gate_s[r0 * 33 + c0 + 9]       = accH[1];
            gate_s[(r0 + 8) * 33 + c0 + 8] = accH[2];
            gate_s[(r0 + 8) * 33 + c0 + 9] = accH[3];
        }
        __syncthreads();

#pragma unroll
        for (int u = 0; u < 2; u++) {
            int p = tid + u * 256;             // 0..511
            int b = p & 63, jj = p >> 6;
            const float* Prow = P + (size_t)tok_s[b] * G4H + bid * 32;
            float gi = gate_s[b * 33 + jj]      + __ldg(&Prow[jj]);
            float gf = gate_s[b * 33 + 8 + jj]  + __ldg(&Prow[8 + jj]);
            float gg = gate_s[b * 33 + 16 + jj] + __ldg(&Prow[16 + jj]);
            float go = gate_s[b * 33 + 24 + jj] + __ldg(&Prow[24 + jj]);
            float c = c_s[p];
            float si = 1.f / (1.f + expf(-gi));
            float sf = 1.f / (1.f + expf(-gf));
            float so = 1.f / (1.f + expf(-go));
            float cn = sf * c + si * tanhf(gg);
            float hn = so * tanhf(cn);
            c_s[p] = cn;
            __nv_bfloat16 hi = __float2bfloat16(hn);
            __nv_bfloat16 lo = __float2bfloat16(hn - __bfloat162float(hi));
            int jg = bid * 8 + jj;
            g_hhi[(s + 1) & 1][b * H_ + jg] = hi;
            g_hlo[(s + 1) & 1][b * H_ + jg] = lo;
            if (!enc) {
                size_t mrow = (size_t)(t * 64 + b) * K2_LOGITS;
                A2out[mrow + jg]        = hi;
                A2out[mrow + 1024 + jg] = lo;
                A2out[mrow + 2048 + jg] = hi;
            }
        }
        GSYNC();
    }
#undef GSYNC
}

// ---------------- launch ------------------------------------------------------------
extern "C" void kernel_launch(void* const* d_in, const int* in_sizes, int n_in,
                              void* d_out, int out_size)
{
    (void)in_sizes; (void)n_in; (void)out_size;
    const int*   seqs    = (const int*)  d_in[1];
    const float* enc_emb = (const float*)d_in[2];
    const float* enc_Wih = (const float*)d_in[3];
    const float* enc_Whh = (const float*)d_in[4];
    const float* enc_b   = (const float*)d_in[5];
    const float* dec_emb = (const float*)d_in[6];
    const float* dec_Wih = (const float*)d_in[7];
    const float* dec_Whh = (const float*)d_in[8];
    const float* dec_b   = (const float*)d_in[9];
    const float* out_W   = (const float*)d_in[10];
    const float* out_b   = (const float*)d_in[11];
    float* out = (float*)d_out;

    float *Penc, *Pdec, *biasr;
    __nv_bfloat16 *A2, *B2, *Wre, *Wrd;
    cudaGetSymbolAddress((void**)&Penc, g_P_enc);
    cudaGetSymbolAddress((void**)&Pdec, g_P_dec);
    cudaGetSymbolAddress((void**)&A2,   g_A2);
    cudaGetSymbolAddress((void**)&B2,   g_B2);
    cudaGetSymbolAddress((void**)&Wre,  g_Wr_e);
    cudaGetSymbolAddress((void**)&Wrd,  g_Wr_d);
    cudaGetSymbolAddress((void**)&biasr, g_bias_r);

    cudaFuncSetAttribute(mma_nt<0>, cudaFuncAttributeMaxDynamicSharedMemorySize, GEMM_SMEM);
    cudaFuncSetAttribute(mma_nt<1>, cudaFuncAttributeMaxDynamicSharedMemorySize, GEMM_SMEM);
    cudaFuncSetAttribute(lstm_rec_mma, cudaFuncAttributeMaxDynamicSharedMemorySize, REC_SMEM);

    // ---- encoder vocab table: P_enc = enc_emb @ enc_Wih'(reordered)^T + b'  [8000,4096]
    split_rows<1, 0><<<(MPAD_TAB * E_ + 255) / 256, 256>>>(enc_emb, A2, V_, MPAD_TAB, E_);
    split_rows<0, 1><<<(G4H * E_ + 255) / 256, 256>>>(enc_Wih, B2, G4H, G4H, E_);
    reorder_bias<<<16, 256>>>(enc_b, biasr);
    mma_nt<0><<<dim3(G4H / 128, MPAD_TAB / 128), 256, GEMM_SMEM>>>(
        A2, B2, biasr, Penc, V_, G4H, K2_TAB, G4H);

    // ---- decoder vocab table
    split_rows<1, 0><<<(MPAD_TAB * E_ + 255) / 256, 256>>>(dec_emb, A2, V_, MPAD_TAB, E_);
    split_rows<0, 1><<<(G4H * E_ + 255) / 256, 256>>>(dec_Wih, B2, G4H, G4H, E_);
    reorder_bias<<<16, 256>>>(dec_b, biasr);
    mma_nt<0><<<dim3(G4H / 128, MPAD_TAB / 128), 256, GEMM_SMEM>>>(
        A2, B2, biasr, Pdec, V_, G4H, K2_TAB, G4H);

    // ---- recurrence weights (reordered + split), logits B operand, A2 cleared
    split_rows<0, 1><<<(G4H * H_ + 255) / 256, 256>>>(enc_Whh, Wre, G4H, G4H, H_);
    split_rows<0, 1><<<(G4H * H_ + 255) / 256, 256>>>(dec_Whh, Wrd, G4H, G4H, H_);
    split_rows<0, 0><<<(NPAD_LOGITS * H_ + 255) / 256, 256>>>(out_W, B2, V_, NPAD_LOGITS, H_);
    {
        size_t n16 = ((size_t)MPAD_LOGITS * K2_LOGITS * 2) / 16;
        zero_buf<<<(unsigned)((n16 + 255) / 256), 256>>>((float4*)A2, n16);
    }

    // ---- serial recurrence (persistent, writes decoder h straight into A2 split form)
    lstm_rec_mma<<<NBLK, 256, REC_SMEM>>>(seqs, Wre, Wrd, A2);

    // ---- logits = Hdec_split @ out_W_split^T + out_b -> [B, 255, V]
    mma_nt<1><<<dim3(NPAD_LOGITS / 128, MPAD_LOGITS / 128), 256, GEMM_SMEM>>>(
        A2, B2, out_b, out, TDEC * B_, V_, K2_LOGITS, V_);
}

// round 12
// speedup vs baseline: 5.7815x; 1.3552x over previous
#include <cuda_runtime.h>
#include <cuda_bf16.h>
#include <math.h>
#include <stdint.h>

// Seq2seq LSTM forward, sm_103a. Pipeline:
//   (1) vocab tables P = embed @ Wih^T + b via HMMA GEMM (split-bf16 3-term)
//   (2) persistent-grid LSTM recurrence (511 serial steps, HMMA per step)
//   (3) one batched logits GEMM over all decoder hidden states
#define NBLK 128
#define B_   64
#define T_   256
#define V_   8000
#define E_   512
#define H_   1024
#define G4H  4096
#define TDEC 255
#define START_TOK 1

#define MPAD_LOGITS 16384
#define NPAD_LOGITS 8192
#define MPAD_TAB    8064
#define K2_LOGITS   3072
#define K2_TAB      1536

#define GEMM_SMEM   98304           // 3 pipeline stages x (16KB A + 16KB B)
// recurrence smem map: W [Whi|Wlo] 131072 | h ring 3x16384 | c 2048 | tok 256
#define RW_OFF      0
#define RH_OFF      131072
#define RC_OFF      180224
#define RT_OFF      182272
#define REC_SMEM    182528

// ---------------- PTX helpers -------------------------------------------------------
__device__ __forceinline__ uint32_t smem_u32(const void* p) {
    uint32_t a;
    asm("{ .reg .u64 t; cvta.to.shared.u64 t, %1; cvt.u32.u64 %0, t; }" : "=r"(a) : "l"(p));
    return a;
}
__device__ __forceinline__ uint32_t sw128(uint32_t off) {
    return off ^ ((off >> 3) & 0x70);
}
__device__ __forceinline__ void cp_async16(uint32_t dst, const void* src) {
    asm volatile("cp.async.cg.shared.global [%0], [%1], 16;" :: "r"(dst), "l"(src) : "memory");
}
#define CP_COMMIT() asm volatile("cp.async.commit_group;" ::: "memory")
template<int N> __device__ __forceinline__ void cp_wait() {
    asm volatile("cp.async.wait_group %0;" :: "n"(N) : "memory");
}
__device__ __forceinline__ void ldsm_x4(uint32_t r[4], uint32_t addr) {
    asm volatile("ldmatrix.sync.aligned.m8n8.x4.shared.b16 {%0,%1,%2,%3}, [%4];"
                 : "=r"(r[0]), "=r"(r[1]), "=r"(r[2]), "=r"(r[3]) : "r"(addr));
}
__device__ __forceinline__ void mma_bf16(float d[4], const uint32_t a[4],
                                         uint32_t b0, uint32_t b1) {
    asm volatile(
        "mma.sync.aligned.m16n8k16.row.col.f32.bf16.bf16.f32 "
        "{%0,%1,%2,%3}, {%4,%5,%6,%7}, {%8,%9}, {%0,%1,%2,%3};"
        : "+f"(d[0]), "+f"(d[1]), "+f"(d[2]), "+f"(d[3])
        : "r"(a[0]), "r"(a[1]), "r"(a[2]), "r"(a[3]), "r"(b0), "r"(b1));
}

// ---------------- device scratch (allocation-free rule) -----------------------------
__device__ float g_P_enc[(size_t)V_ * G4H];
__device__ float g_P_dec[(size_t)V_ * G4H];
__device__ __nv_bfloat16 g_A2[(size_t)MPAD_LOGITS * K2_LOGITS];
__device__ __nv_bfloat16 g_B2[(size_t)NPAD_LOGITS * K2_LOGITS];
__device__ __nv_bfloat16 g_Wr_e[(size_t)G4H * 2048];    // rows reordered, [Whi | Wlo]
__device__ __nv_bfloat16 g_Wr_d[(size_t)G4H * 2048];
__device__ __nv_bfloat16 g_hhi[2][B_ * H_];
__device__ __nv_bfloat16 g_hlo[2][B_ * H_];
__device__ float g_bias_r[G4H];
__device__ unsigned g_arrive = 0;
__device__ unsigned g_phase  = 0;

// ---------------- split / reorder / zero helpers -----------------------------------
// MODEA=1 packs [hi|lo|hi] (A operand, 3K cols); MODEA=0 packs [hi|hi|lo] (B operand).
template<int MODEA, int REORD>
__global__ void split_rows(const float* __restrict__ X, __nv_bfloat16* __restrict__ Y,
                           int M_in, int M_pad, int K)
{
    int idx = blockIdx.x * blockDim.x + threadIdx.x;
    if (idx >= M_pad * K) return;
    int m = idx / K, k = idx - m * K;
    int src = m;
    if (REORD) {
        int blk = m >> 5, r = m & 31;
        src = (r >> 3) * H_ + blk * 8 + (r & 7);
    }
    float x = (src < M_in) ? X[(size_t)src * K + k] : 0.f;
    __nv_bfloat16 hi = __float2bfloat16(x);
    __nv_bfloat16 lo = __float2bfloat16(x - __bfloat162float(hi));
    size_t rb = (size_t)m * (3 * K);
    Y[rb + k]         = hi;
    Y[rb + K + k]     = MODEA ? lo : hi;
    Y[rb + 2 * K + k] = MODEA ? hi : lo;
}

// Recurrence weight split: reordered gate rows, two K-blocks [hi | lo]
__global__ void split2_reord(const float* __restrict__ X, __nv_bfloat16* __restrict__ Y,
                             int K)
{
    int idx = blockIdx.x * blockDim.x + threadIdx.x;
    if (idx >= G4H * K) return;
    int m = idx / K, k = idx - m * K;
    int blk = m >> 5, r = m & 31;
    int src = (r >> 3) * H_ + blk * 8 + (r & 7);
    float x = X[(size_t)src * K + k];
    __nv_bfloat16 hi = __float2bfloat16(x);
    __nv_bfloat16 lo = __float2bfloat16(x - __bfloat162float(hi));
    size_t rb = (size_t)m * (2 * K);
    Y[rb + k]     = hi;
    Y[rb + K + k] = lo;
}

__global__ void reorder_bias(const float* __restrict__ b, float* __restrict__ br) {
    int m = blockIdx.x * blockDim.x + threadIdx.x;
    if (m >= G4H) return;
    int blk = m >> 5, r = m & 31;
    br[m] = b[(r >> 3) * H_ + blk * 8 + (r & 7)];
}

__global__ void zero_buf(float4* p, size_t n16) {
    size_t i = (size_t)blockIdx.x * blockDim.x + threadIdx.x;
    if (i < n16) p[i] = make_float4(0.f, 0.f, 0.f, 0.f);
}

// ---------------- HMMA GEMM: C[M,N] = A2[M,K2] @ B2[N,K2]^T + bias ------------------
// 128x128 tiles, 64-col bf16 K-chunks (128B rows, sw128), 3-stage ring, 2 CTAs/SM.
// MODE 0: row-major C.  MODE 1: logits remap m=t*64+b -> C[(b*255+t)*ldC + n]
template<int MODE>
__global__ void __launch_bounds__(256, 2) mma_nt(
    const __nv_bfloat16* __restrict__ A2, const __nv_bfloat16* __restrict__ B2,
    const float* __restrict__ bias, float* __restrict__ C,
    int M_eff, int N_eff, int K2, int ldC)
{
    extern __shared__ __align__(1024) char dsm[];
    const uint32_t sb = smem_u32(dsm);
    const int tid = threadIdx.x;
    const int wid = tid >> 5, lid = tid & 31;
    const int wm = wid & 3, wn = wid >> 2;
    const int bm = blockIdx.y * 128, bn = blockIdx.x * 128;
    const int nch = K2 / 64;

    auto loadT = [&](int ch) {
        int stg = ch % 3;
#pragma unroll
        for (int j = 0; j < 4; j++) {
            int i = tid + j * 256;
            int r = i >> 3, cb = (i & 7) * 16;
            cp_async16(sb + stg * 16384 + sw128((uint32_t)(r * 128 + cb)),
                       (const char*)A2 + ((size_t)(bm + r) * K2 + ch * 64) * 2 + cb);
        }
#pragma unroll
        for (int j = 0; j < 4; j++) {
            int i = tid + j * 256;
            int r = i >> 3, cb = (i & 7) * 16;
            cp_async16(sb + 49152 + stg * 16384 + sw128((uint32_t)(r * 128 + cb)),
                       (const char*)B2 + ((size_t)(bn + r) * K2 + ch * 64) * 2 + cb);
        }
        CP_COMMIT();
    };

    float acc[2][8][4];
#pragma unroll
    for (int i = 0; i < 2; i++)
#pragma unroll
        for (int j = 0; j < 8; j++)
#pragma unroll
            for (int q = 0; q < 4; q++) acc[i][j][q] = 0.f;

    loadT(0); loadT(1);
    for (int i = 0; i < nch; i++) {
        if (i < nch - 1) cp_wait<1>(); else cp_wait<0>();
        __syncthreads();
        if (i + 2 < nch) loadT(i + 2);   // targets stage (i-1)%3, vacated pre-sync
        const uint32_t ab = sb + (i % 3) * 16384;
        const uint32_t bb = sb + 49152 + (i % 3) * 16384;
#pragma unroll
        for (int ks = 0; ks < 4; ks++) {
            const uint32_t kb = (uint32_t)((ks * 16 + ((lid >> 4) << 3)) * 2);
            uint32_t a[2][4], b[4][4];
#pragma unroll
            for (int mi = 0; mi < 2; mi++)
                ldsm_x4(a[mi], ab + sw128((uint32_t)((wm * 32 + mi * 16 + (lid & 15)) * 128) + kb));
#pragma unroll
            for (int ni = 0; ni < 4; ni++)
                ldsm_x4(b[ni], bb + sw128((uint32_t)((wn * 64 + ni * 16 + (lid & 15)) * 128) + kb));
#pragma unroll
            for (int mi = 0; mi < 2; mi++)
#pragma unroll
                for (int ni = 0; ni < 4; ni++) {
                    mma_bf16(acc[mi][2 * ni + 0], a[mi], b[ni][0], b[ni][2]);
                    mma_bf16(acc[mi][2 * ni + 1], a[mi], b[ni][1], b[ni][3]);
                }
        }
    }

#pragma unroll
    for (int mi = 0; mi < 2; mi++) {
        int m0 = bm + wm * 32 + mi * 16 + (lid >> 2);
#pragma unroll
        for (int half = 0; half < 2; half++) {
            int m = m0 + half * 8;
            if (m >= M_eff) continue;
            size_t obase;
            if (MODE == 0) obase = (size_t)m * ldC;
            else {
                int t = m >> 6, b = m & 63;
                obase = ((size_t)b * TDEC + t) * ldC;
            }
#pragma unroll
            for (int nj = 0; nj < 8; nj++) {
                int n = bn + wn * 64 + nj * 8 + (lid & 3) * 2;
                float v0 = acc[mi][nj][half * 2 + 0];
                float v1 = acc[mi][nj][half * 2 + 1];
                if (n < N_eff)     C[obase + n]     = v0 + __ldg(&bias[n]);
                if (n + 1 < N_eff) C[obase + n + 1] = v1 + __ldg(&bias[n + 1]);
            }
        }
    }
}

// ---------------- persistent HMMA LSTM recurrence ----------------------------------
// 128 blocks x 256 thr; block owns 32 reordered gate rows (4 gates x 8 hidden units).
// W' = [Whi|Wlo] (32 x 2048 bf16, sw128) stays in smem across all 511 steps.
// Each of 16 k-chunks per step issues the 3 split-bf16 terms into fp32 accumulators:
//   gates += h_hi*Whi + h_lo*Whi + h_hi*Wlo
__global__ void __launch_bounds__(256, 1) lstm_rec_mma(
    const int* __restrict__ seqs,
    const __nv_bfloat16* __restrict__ Wr_e,
    const __nv_bfloat16* __restrict__ Wr_d,
    __nv_bfloat16* __restrict__ A2out)
{
    extern __shared__ __align__(1024) char dsm[];
    const uint32_t sb = smem_u32(dsm);
    float* gate_s = (float*)(dsm + RH_OFF);      // [64][33], aliases h-ring stage 0
    float* c_s    = (float*)(dsm + RC_OFF);      // [512]: p = jj*64 + b
    int*   tok_s  = (int*)  (dsm + RT_OFF);

    const int tid = threadIdx.x;
    const int bid = blockIdx.x;
    const int wid = tid >> 5, lid = tid & 31;
    const int wm = wid & 3, wn = wid >> 2;

    unsigned base = 0;
    if (tid == 0) base = atomicAdd(&g_phase, 0u);   // replay-safe phase baseline
    unsigned tgt = 0;

    for (int i = bid * 256 + tid; i < B_ * H_; i += NBLK * 256) {
        g_hhi[0][i] = __float2bfloat16(0.f);
        g_hlo[0][i] = __float2bfloat16(0.f);
    }
    c_s[tid] = 0.f; c_s[tid + 256] = 0.f;

    // W loader: 32 rows x 4096 bytes each; smem chunk ci holds byte-cols [ci*128, +128)
    auto loadW = [&](const __nv_bfloat16* Wsrc) {
#pragma unroll
        for (int j = 0; j < 32; j++) {
            int i = tid + j * 256;
            int row = i >> 8;
            int cb  = (i & 255) * 16;
            int ci  = cb >> 7, inner = cb & 127;
            cp_async16(sb + RW_OFF + ci * 4096 + sw128((uint32_t)(row * 128 + inner)),
                       (const char*)Wsrc + (size_t)(bid * 32 + row) * 4096 + cb);
        }
        CP_COMMIT();
    };
    loadW(Wr_e);   // drained by the first chunk-loop wait

#define GSYNC() do {                                                     \
    __syncthreads();                                                     \
    if (tid == 0) {                                                      \
        ++tgt;                                                           \
        __threadfence();                                                 \
        unsigned prev_ = atomicAdd(&g_arrive, 1u);                       \
        if (prev_ == NBLK - 1) {                                         \
            atomicExch(&g_arrive, 0u);                                   \
            __threadfence();                                             \
            atomicAdd(&g_phase, 1u);                                     \
        } else {                                                         \
            while ((unsigned)(atomicAdd(&g_phase, 0u) - base) < tgt)     \
                __nanosleep(64);                                         \
            __threadfence();                                             \
        }                                                                \
    }                                                                    \
    __syncthreads();                                                     \
} while (0)

    GSYNC();   // h0 visible grid-wide

    for (int s = 0; s < T_ + TDEC; s++) {
        const bool enc = (s < T_);
        const int t = enc ? s : s - T_;
        const float* __restrict__ P = enc ? g_P_enc : g_P_dec;
        const __nv_bfloat16* __restrict__ hhi = g_hhi[s & 1];
        const __nv_bfloat16* __restrict__ hlo = g_hlo[s & 1];

        if (s == T_) loadW(Wr_d);            // decoder weights; drained at chunk-0 wait
        if (tid < B_)
            tok_s[tid] = enc ? seqs[tid * T_ + t]
                             : (t == 0 ? START_TOK : seqs[tid * T_ + t]);

        // h chunk loader: one ring stage = hhi chunk (8KB) + hlo chunk (8KB)
        auto loadH = [&](int ch) {
            uint32_t stg = sb + RH_OFF + (ch % 3) * 16384;
            int j0 = ch * 64;
#pragma unroll
            for (int j = 0; j < 2; j++) {
                int i = tid + j * 256;
                int r = i >> 3, cb = (i & 7) * 16;
                uint32_t off = sw128((uint32_t)(r * 128 + cb));
                cp_async16(stg + off,        (const char*)hhi + (size_t)r * 2048 + j0 * 2 + cb);
                cp_async16(stg + 8192 + off, (const char*)hlo + (size_t)r * 2048 + j0 * 2 + cb);
            }
            CP_COMMIT();
        };

        float accL[4] = {0.f, 0.f, 0.f, 0.f};
        float accH[4] = {0.f, 0.f, 0.f, 0.f};
        loadH(0); loadH(1);

        for (int ch = 0; ch < 16; ch++) {
            if (ch < 15) cp_wait<1>(); else cp_wait<0>();
            __syncthreads();
            if (ch + 2 < 16) loadH(ch + 2);  // targets stage (ch-1)%3, vacated pre-sync
            const uint32_t hbh = sb + RH_OFF + (ch % 3) * 16384;
            const uint32_t hbl = hbh + 8192;
            const uint32_t wbh = sb + RW_OFF + ch * 4096;
            const uint32_t wbl = sb + RW_OFF + (ch + 16) * 4096;
#pragma unroll
            for (int ks = 0; ks < 4; ks++) {
                const uint32_t kb = (uint32_t)((ks * 16 + ((lid >> 4) << 3)) * 2);
                const uint32_t arow = sw128((uint32_t)((wm * 16 + (lid & 15)) * 128) + kb);
                const uint32_t brow = sw128((uint32_t)((wn * 16 + (lid & 15)) * 128) + kb);
                uint32_t ah[4], al[4], bh[4], bl[4];
                ldsm_x4(ah, hbh + arow);
                ldsm_x4(al, hbl + arow);
                ldsm_x4(bh, wbh + brow);
                ldsm_x4(bl, wbl + brow);
                mma_bf16(accL, ah, bh[0], bh[2]); mma_bf16(accH, ah, bh[1], bh[3]);
                mma_bf16(accL, al, bh[0], bh[2]); mma_bf16(accH, al, bh[1], bh[3]);
                mma_bf16(accL, ah, bl[0], bl[2]); mma_bf16(accH, ah, bl[1], bl[3]);
            }
        }
        __syncthreads();                     // all ring reads done -> gate_s alias safe

        {
            int r0 = wm * 16 + (lid >> 2);
            int c0 = wn * 16 + (lid & 3) * 2;
            gate_s[r0 * 33 + c0]           = accL[0];
            gate_s[r0 * 33 + c0 + 1]       = accL[1];
            gate_s[(r0 + 8) * 33 + c0]     = accL[2];
            gate_s[(r0 + 8) * 33 + c0 + 1] = accL[3];
            gate_s[r0 * 33 + c0 + 8]       = accH[0];
            gate_s[r0 * 33 + c0 + 9]       = accH[1];
            gate_s[(r0 + 8) * 33 + c0 + 8] = accH[2];
            gate_s[(r0 + 8) * 33 + c0 + 9] = accH[3];
        }
        __syncthreads();

#pragma unroll
        for (int u = 0; u < 2; u++) {
            int p = tid + u * 256;
            int b = p & 63, jj = p >> 6;
            const float* Prow = P + (size_t)tok_s[b] * G4H + bid * 32;
            float gi = gate_s[b * 33 + jj]      + __ldg(&Prow[jj]);
            float gf = gate_s[b * 33 + 8 + jj]  + __ldg(&Prow[8 + jj]);
            float gg = gate_s[b * 33 + 16 + jj] + __ldg(&Prow[16 + jj]);
            float go = gate_s[b * 33 + 24 + jj] + __ldg(&Prow[24 + jj]);
            float c = c_s[p];
            float si = 1.f / (1.f + expf(-gi));
            float sf = 1.f / (1.f + expf(-gf));
            float so = 1.f / (1.f + expf(-go));
            float cn = sf * c + si * tanhf(gg);
            float hn = so * tanhf(cn);
            c_s[p] = cn;
            __nv_bfloat16 hi = __float2bfloat16(hn);
            __nv_bfloat16 lo = __float2bfloat16(hn - __bfloat162float(hi));
            int jg = bid * 8 + jj;
            g_hhi[(s + 1) & 1][b * H_ + jg] = hi;
            g_hlo[(s + 1) & 1][b * H_ + jg] = lo;
            if (!enc) {
                size_t mrow = (size_t)(t * 64 + b) * K2_LOGITS;
                A2out[mrow + jg]        = hi;
                A2out[mrow + 1024 + jg] = lo;
                A2out[mrow + 2048 + jg] = hi;
            }
        }
        GSYNC();
    }
#undef GSYNC
}

// ---------------- launch ------------------------------------------------------------
extern "C" void kernel_launch(void* const* d_in, const int* in_sizes, int n_in,
                              void* d_out, int out_size)
{
    (void)in_sizes; (void)n_in; (void)out_size;
    const int*   seqs    = (const int*)  d_in[1];
    const float* enc_emb = (const float*)d_in[2];
    const float* enc_Wih = (const float*)d_in[3];
    const float* enc_Whh = (const float*)d_in[4];
    const float* enc_b   = (const float*)d_in[5];
    const float* dec_emb = (const float*)d_in[6];
    const float* dec_Wih = (const float*)d_in[7];
    const float* dec_Whh = (const float*)d_in[8];
    const float* dec_b   = (const float*)d_in[9];
    const float* out_W   = (const float*)d_in[10];
    const float* out_b   = (const float*)d_in[11];
    float* out = (float*)d_out;

    float *Penc, *Pdec, *biasr;
    __nv_bfloat16 *A2, *B2, *Wre, *Wrd;
    cudaGetSymbolAddress((void**)&Penc, g_P_enc);
    cudaGetSymbolAddress((void**)&Pdec, g_P_dec);
    cudaGetSymbolAddress((void**)&A2,   g_A2);
    cudaGetSymbolAddress((void**)&B2,   g_B2);
    cudaGetSymbolAddress((void**)&Wre,  g_Wr_e);
    cudaGetSymbolAddress((void**)&Wrd,  g_Wr_d);
    cudaGetSymbolAddress((void**)&biasr, g_bias_r);

    cudaFuncSetAttribute(mma_nt<0>, cudaFuncAttributeMaxDynamicSharedMemorySize, GEMM_SMEM);
    cudaFuncSetAttribute(mma_nt<1>, cudaFuncAttributeMaxDynamicSharedMemorySize, GEMM_SMEM);
    cudaFuncSetAttribute(lstm_rec_mma, cudaFuncAttributeMaxDynamicSharedMemorySize, REC_SMEM);

    // encoder vocab table: P_enc = enc_emb @ enc_Wih'(reordered)^T + b'  [8000,4096]
    split_rows<1, 0><<<(MPAD_TAB * E_ + 255) / 256, 256>>>(enc_emb, A2, V_, MPAD_TAB, E_);
    split_rows<0, 1><<<(G4H * E_ + 255) / 256, 256>>>(enc_Wih, B2, G4H, G4H, E_);
    reorder_bias<<<16, 256>>>(enc_b, biasr);
    mma_nt<0><<<dim3(G4H / 128, MPAD_TAB / 128), 256, GEMM_SMEM>>>(
        A2, B2, biasr, Penc, V_, G4H, K2_TAB, G4H);

    // decoder vocab table
    split_rows<1, 0><<<(MPAD_TAB * E_ + 255) / 256, 256>>>(dec_emb, A2, V_, MPAD_TAB, E_);
    split_rows<0, 1><<<(G4H * E_ + 255) / 256, 256>>>(dec_Wih, B2, G4H, G4H, E_);
    reorder_bias<<<16, 256>>>(dec_b, biasr);
    mma_nt<0><<<dim3(G4H / 128, MPAD_TAB / 128), 256, GEMM_SMEM>>>(
        A2, B2, biasr, Pdec, V_, G4H, K2_TAB, G4H);

    // recurrence weights (reordered, [hi|lo]); logits B operand; clear A2
    split2_reord<<<(G4H * H_ + 255) / 256, 256>>>(enc_Whh, Wre, H_);
    split2_reord<<<(G4H * H_ + 255) / 256, 256>>>(dec_Whh, Wrd, H_);
    split_rows<0, 0><<<(NPAD_LOGITS * H_ + 255) / 256, 256>>>(out_W, B2, V_, NPAD_LOGITS, H_);
    {
        size_t n16 = ((size_t)MPAD_LOGITS * K2_LOGITS * 2) / 16;
        zero_buf<<<(unsigned)((n16 + 255) / 256), 256>>>((float4*)A2, n16);
    }

    // serial recurrence (persistent grid; decoder h written directly into A2 split form)
    lstm_rec_mma<<<NBLK, 256, REC_SMEM>>>(seqs, Wre, Wrd, A2);

    // logits = Hdec_split @ out_W_split^T + out_b -> [B, 255, V]
    mma_nt<1><<<dim3(NPAD_LOGITS / 128, MPAD_LOGITS / 128), 256, GEMM_SMEM>>>(
        A2, B2, out_b, out, TDEC * B_, V_, K2_LOGITS, V_);
}

// round 13
// speedup vs baseline: 6.6973x; 1.1584x over previous
#include <cuda_runtime.h>
#include <cuda_bf16.h>
#include <cuda_fp16.h>
#include <math.h>
#include <stdint.h>

// Seq2seq LSTM forward, sm_103a.
//   (1) vocab tables P = embed @ Wih^T + b  (HMMA, split-bf16 3-term)
//   (2) persistent-grid LSTM recurrence: h in SINGLE fp16 (h in [-1,1]),
//       W split into fp16 hi+lo -> 2 MMA terms, h traffic halved
//   (3) batched logits GEMM (HMMA, split-bf16 3-term)
#define NBLK 128
#define B_   64
#define T_   256
#define V_   8000
#define E_   512
#define H_   1024
#define G4H  4096
#define TDEC 255
#define START_TOK 1

#define MPAD_LOGITS 16384
#define NPAD_LOGITS 8192
#define MPAD_TAB    8064
#define K2_LOGITS   3072
#define K2_TAB      1536

#define GEMM_SMEM   98304           // 3 stages x (16KB A + 16KB B)
// recurrence smem: W16 [hi|lo] 131072 | h ring 3x16384 | c 2048 | tok 256
#define RW_OFF      0
#define RH_OFF      131072
#define RC_OFF      180224
#define RT_OFF      182272
#define REC_SMEM    182528

// ---------------- PTX helpers -------------------------------------------------------
__device__ __forceinline__ uint32_t smem_u32(const void* p) {
    uint32_t a;
    asm("{ .reg .u64 t; cvta.to.shared.u64 t, %1; cvt.u32.u64 %0, t; }" : "=r"(a) : "l"(p));
    return a;
}
__device__ __forceinline__ uint32_t sw128(uint32_t off) {
    return off ^ ((off >> 3) & 0x70);
}
__device__ __forceinline__ void cp_async16(uint32_t dst, const void* src) {
    asm volatile("cp.async.cg.shared.global [%0], [%1], 16;" :: "r"(dst), "l"(src) : "memory");
}
#define CP_COMMIT() asm volatile("cp.async.commit_group;" ::: "memory")
template<int N> __device__ __forceinline__ void cp_wait() {
    asm volatile("cp.async.wait_group %0;" :: "n"(N) : "memory");
}
__device__ __forceinline__ void ldsm_x4(uint32_t r[4], uint32_t addr) {
    asm volatile("ldmatrix.sync.aligned.m8n8.x4.shared.b16 {%0,%1,%2,%3}, [%4];"
                 : "=r"(r[0]), "=r"(r[1]), "=r"(r[2]), "=r"(r[3]) : "r"(addr));
}
__device__ __forceinline__ void mma_bf16(float d[4], const uint32_t a[4],
                                         uint32_t b0, uint32_t b1) {
    asm volatile(
        "mma.sync.aligned.m16n8k16.row.col.f32.bf16.bf16.f32 "
        "{%0,%1,%2,%3}, {%4,%5,%6,%7}, {%8,%9}, {%0,%1,%2,%3};"
        : "+f"(d[0]), "+f"(d[1]), "+f"(d[2]), "+f"(d[3])
        : "r"(a[0]), "r"(a[1]), "r"(a[2]), "r"(a[3]), "r"(b0), "r"(b1));
}
__device__ __forceinline__ void mma_f16(float d[4], const uint32_t a[4],
                                        uint32_t b0, uint32_t b1) {
    asm volatile(
        "mma.sync.aligned.m16n8k16.row.col.f32.f16.f16.f32 "
        "{%0,%1,%2,%3}, {%4,%5,%6,%7}, {%8,%9}, {%0,%1,%2,%3};"
        : "+f"(d[0]), "+f"(d[1]), "+f"(d[2]), "+f"(d[3])
        : "r"(a[0]), "r"(a[1]), "r"(a[2]), "r"(a[3]), "r"(b0), "r"(b1));
}

// ---------------- device scratch (allocation-free rule) -----------------------------
__device__ float g_P_enc[(size_t)V_ * G4H];
__device__ float g_P_dec[(size_t)V_ * G4H];
__device__ __nv_bfloat16 g_A2[(size_t)MPAD_LOGITS * K2_LOGITS];
__device__ __nv_bfloat16 g_B2[(size_t)NPAD_LOGITS * K2_LOGITS];
__device__ __half g_W16_e[(size_t)G4H * 2048];   // reordered rows, [W16hi | W16lo]
__device__ __half g_W16_d[(size_t)G4H * 2048];
__device__ __half g_h16[2][B_ * H_];             // double-buffered fp16 hidden state
__device__ float g_bias_r[G4H];
__device__ unsigned g_arrive = 0;
__device__ unsigned g_phase  = 0;

// ---------------- split / reorder / zero helpers -----------------------------------
// MODEA=1 packs [hi|lo|hi] (A operand, 3K cols); MODEA=0 packs [hi|hi|lo] (B operand).
template<int MODEA, int REORD>
__global__ void split_rows(const float* __restrict__ X, __nv_bfloat16* __restrict__ Y,
                           int M_in, int M_pad, int K)
{
    int idx = blockIdx.x * blockDim.x + threadIdx.x;
    if (idx >= M_pad * K) return;
    int m = idx / K, k = idx - m * K;
    int src = m;
    if (REORD) {
        int blk = m >> 5, r = m & 31;
        src = (r >> 3) * H_ + blk * 8 + (r & 7);
    }
    float x = (src < M_in) ? X[(size_t)src * K + k] : 0.f;
    __nv_bfloat16 hi = __float2bfloat16(x);
    __nv_bfloat16 lo = __float2bfloat16(x - __bfloat162float(hi));
    size_t rb = (size_t)m * (3 * K);
    Y[rb + k]         = hi;
    Y[rb + K + k]     = MODEA ? lo : hi;
    Y[rb + 2 * K + k] = MODEA ? hi : lo;
}

// Recurrence weights: reordered gate rows, fp16 two-term [hi | lo]
__global__ void split2h_reord(const float* __restrict__ X, __half* __restrict__ Y,
                              int K)
{
    int idx = blockIdx.x * blockDim.x + threadIdx.x;
    if (idx >= G4H * K) return;
    int m = idx / K, k = idx - m * K;
    int blk = m >> 5, r = m & 31;
    int src = (r >> 3) * H_ + blk * 8 + (r & 7);
    float x = X[(size_t)src * K + k];
    __half hi = __float2half_rn(x);
    __half lo = __float2half_rn(x - __half2float(hi));
    size_t rb = (size_t)m * (2 * K);
    Y[rb + k]     = hi;
    Y[rb + K + k] = lo;
}

__global__ void reorder_bias(const float* __restrict__ b, float* __restrict__ br) {
    int m = blockIdx.x * blockDim.x + threadIdx.x;
    if (m >= G4H) return;
    int blk = m >> 5, r = m & 31;
    br[m] = b[(r >> 3) * H_ + blk * 8 + (r & 7)];
}

__global__ void zero_buf(float4* p, size_t n16) {
    size_t i = (size_t)blockIdx.x * blockDim.x + threadIdx.x;
    if (i < n16) p[i] = make_float4(0.f, 0.f, 0.f, 0.f);
}

// ---------------- HMMA GEMM: C[M,N] = A2[M,K2] @ B2[N,K2]^T + bias ------------------
// 128x128 tiles, 64-col bf16 K-chunks (128B rows, sw128), 3-stage ring, 2 CTAs/SM.
// MODE 0: row-major C.  MODE 1: logits remap m=t*64+b -> C[(b*255+t)*ldC + n]
template<int MODE>
__global__ void __launch_bounds__(256, 2) mma_nt(
    const __nv_bfloat16* __restrict__ A2, const __nv_bfloat16* __restrict__ B2,
    const float* __restrict__ bias, float* __restrict__ C,
    int M_eff, int N_eff, int K2, int ldC)
{
    extern __shared__ __align__(1024) char dsm[];
    const uint32_t sb = smem_u32(dsm);
    const int tid = threadIdx.x;
    const int wid = tid >> 5, lid = tid & 31;
    const int wm = wid & 3, wn = wid >> 2;
    const int bm = blockIdx.y * 128, bn = blockIdx.x * 128;
    const int nch = K2 / 64;

    auto loadT = [&](int ch) {
        int stg = ch % 3;
#pragma unroll
        for (int j = 0; j < 4; j++) {
            int i = tid + j * 256;
            int r = i >> 3, cb = (i & 7) * 16;
            cp_async16(sb + stg * 16384 + sw128((uint32_t)(r * 128 + cb)),
                       (const char*)A2 + ((size_t)(bm + r) * K2 + ch * 64) * 2 + cb);
        }
#pragma unroll
        for (int j = 0; j < 4; j++) {
            int i = tid + j * 256;
            int r = i >> 3, cb = (i & 7) * 16;
            cp_async16(sb + 49152 + stg * 16384 + sw128((uint32_t)(r * 128 + cb)),
                       (const char*)B2 + ((size_t)(bn + r) * K2 + ch * 64) * 2 + cb);
        }
        CP_COMMIT();
    };

    float acc[2][8][4];
#pragma unroll
    for (int i = 0; i < 2; i++)
#pragma unroll
        for (int j = 0; j < 8; j++)
#pragma unroll
            for (int q = 0; q < 4; q++) acc[i][j][q] = 0.f;

    loadT(0); loadT(1);
    for (int i = 0; i < nch; i++) {
        if (i < nch - 1) cp_wait<1>(); else cp_wait<0>();
        __syncthreads();
        if (i + 2 < nch) loadT(i + 2);   // targets stage (i-1)%3, vacated pre-sync
        const uint32_t ab = sb + (i % 3) * 16384;
        const uint32_t bb = sb + 49152 + (i % 3) * 16384;
#pragma unroll
        for (int ks = 0; ks < 4; ks++) {
            const uint32_t kb = (uint32_t)((ks * 16 + ((lid >> 4) << 3)) * 2);
            uint32_t a[2][4], b[4][4];
#pragma unroll
            for (int mi = 0; mi < 2; mi++)
                ldsm_x4(a[mi], ab + sw128((uint32_t)((wm * 32 + mi * 16 + (lid & 15)) * 128) + kb));
#pragma unroll
            for (int ni = 0; ni < 4; ni++)
                ldsm_x4(b[ni], bb + sw128((uint32_t)((wn * 64 + ni * 16 + (lid & 15)) * 128) + kb));
#pragma unroll
            for (int mi = 0; mi < 2; mi++)
#pragma unroll
                for (int ni = 0; ni < 4; ni++) {
                    mma_bf16(acc[mi][2 * ni + 0], a[mi], b[ni][0], b[ni][2]);
                    mma_bf16(acc[mi][2 * ni + 1], a[mi], b[ni][1], b[ni][3]);
                }
        }
    }

#pragma unroll
    for (int mi = 0; mi < 2; mi++) {
        int m0 = bm + wm * 32 + mi * 16 + (lid >> 2);
#pragma unroll
        for (int half = 0; half < 2; half++) {
            int m = m0 + half * 8;
            if (m >= M_eff) continue;
            size_t obase;
            if (MODE == 0) obase = (size_t)m * ldC;
            else {
                int t = m >> 6, b = m & 63;
                obase = ((size_t)b * TDEC + t) * ldC;
            }
#pragma unroll
            for (int nj = 0; nj < 8; nj++) {
                int n = bn + wn * 64 + nj * 8 + (lid & 3) * 2;
                float v0 = acc[mi][nj][half * 2 + 0];
                float v1 = acc[mi][nj][half * 2 + 1];
                if (n < N_eff)     C[obase + n]     = v0 + __ldg(&bias[n]);
                if (n + 1 < N_eff) C[obase + n + 1] = v1 + __ldg(&bias[n + 1]);
            }
        }
    }
}

// ---------------- persistent HMMA LSTM recurrence (fp16 h, 2-term) ------------------
// 128 blocks x 256 thr; block owns 32 reordered gate rows (4 gates x 8 hidden units).
// W16' = [hi|lo] (32 x 2048 fp16) resident in smem across all 511 steps.
// 8 k-chunks of 128 cols/step; per chunk: gates += h16*W16hi + h16*W16lo (fp32 accum).
__global__ void __launch_bounds__(256, 1) lstm_rec_mma(
    const int* __restrict__ seqs,
    const __half* __restrict__ W16_e,
    const __half* __restrict__ W16_d,
    __nv_bfloat16* __restrict__ A2out)
{
    extern __shared__ __align__(1024) char dsm[];
    const uint32_t sb = smem_u32(dsm);
    float* gate_s = (float*)(dsm + RH_OFF);      // [64][33], aliases h-ring stage 0
    float* c_s    = (float*)(dsm + RC_OFF);      // [512]: p = jj*64 + b
    int*   tok_s  = (int*)  (dsm + RT_OFF);

    const int tid = threadIdx.x;
    const int bid = blockIdx.x;
    const int wid = tid >> 5, lid = tid & 31;
    const int wm = wid & 3, wn = wid >> 2;

    unsigned base = 0;
    if (tid == 0) base = atomicAdd(&g_phase, 0u);   // replay-safe phase baseline
    unsigned tgt = 0;

    for (int i = bid * 256 + tid; i < B_ * H_; i += NBLK * 256)
        g_h16[0][i] = __float2half_rn(0.f);
    c_s[tid] = 0.f; c_s[tid + 256] = 0.f;

    // W loader: 32 rows x 4096 bytes; smem chunk ci holds byte-cols [ci*128, +128)
    auto loadW = [&](const __half* Wsrc) {
#pragma unroll
        for (int j = 0; j < 32; j++) {
            int i = tid + j * 256;
            int row = i >> 8;
            int cb  = (i & 255) * 16;
            int ci  = cb >> 7, inner = cb & 127;
            cp_async16(sb + RW_OFF + ci * 4096 + sw128((uint32_t)(row * 128 + inner)),
                       (const char*)Wsrc + (size_t)(bid * 32 + row) * 4096 + cb);
        }
        CP_COMMIT();
    };
    loadW(W16_e);   // drained by the first chunk-loop wait

#define GSYNC() do {                                                     \
    __syncthreads();                                                     \
    if (tid == 0) {                                                      \
        ++tgt;                                                           \
        __threadfence();                                                 \
        unsigned prev_ = atomicAdd(&g_arrive, 1u);                       \
        if (prev_ == NBLK - 1) {                                         \
            atomicExch(&g_arrive, 0u);                                   \
            __threadfence();                                             \
            atomicAdd(&g_phase, 1u);                                     \
        } else {                                                         \
            volatile unsigned* vp_ = &g_phase;                           \
            while ((unsigned)(*vp_ - base) < tgt)                        \
                __nanosleep(32);                                         \
            __threadfence();                                             \
        }                                                                \
    }                                                                    \
    __syncthreads();                                                     \
} while (0)

    GSYNC();   // h0 visible grid-wide

    for (int s = 0; s < T_ + TDEC; s++) {
        const bool enc = (s < T_);
        const int t = enc ? s : s - T_;
        const float* __restrict__ P = enc ? g_P_enc : g_P_dec;
        const __half* __restrict__ h16 = g_h16[s & 1];

        if (s == T_) loadW(W16_d);           // decoder weights; drained at chunk-0 wait
        if (tid < B_)
            tok_s[tid] = enc ? seqs[tid * T_ + t]
                             : (t == 0 ? START_TOK : seqs[tid * T_ + t]);

        // h chunk loader: 128 fp16 cols = two 64-col sw128 tiles (8KB each)
        auto loadH = [&](int ch) {
            uint32_t stg = sb + RH_OFF + (ch % 3) * 16384;
#pragma unroll
            for (int j = 0; j < 4; j++) {
                int i = tid + j * 256;       // 0..1023
                int r = i >> 4;              // batch row 0..63
                int seg = i & 15;
                int half = seg >> 3, cb = (seg & 7) * 16;
                uint32_t off = sw128((uint32_t)(r * 128 + cb));
                cp_async16(stg + half * 8192 + off,
                           (const char*)h16 + (size_t)r * 2048 + ch * 256 + half * 128 + cb);
            }
            CP_COMMIT();
        };

        float accL[4] = {0.f, 0.f, 0.f, 0.f};
        float accH[4] = {0.f, 0.f, 0.f, 0.f};
        loadH(0); loadH(1);

        for (int ch = 0; ch < 8; ch++) {
            if (ch < 7) cp_wait<1>(); else cp_wait<0>();
            __syncthreads();
            if (ch + 2 < 8) loadH(ch + 2);   // targets stage (ch-1)%3, vacated pre-sync
            const uint32_t hstage = sb + RH_OFF + (ch % 3) * 16384;
#pragma unroll
            for (int half = 0; half < 2; half++) {
                const uint32_t hb  = hstage + half * 8192;
                const uint32_t wbh = sb + RW_OFF + (2 * ch + half) * 4096;
                const uint32_t wbl = sb + RW_OFF + (16 + 2 * ch + half) * 4096;
#pragma unroll
                for (int ks = 0; ks < 4; ks++) {
                    const uint32_t kb = (uint32_t)((ks * 16 + ((lid >> 4) << 3)) * 2);
                    const uint32_t arow = sw128((uint32_t)((wm * 16 + (lid & 15)) * 128) + kb);
                    const uint32_t brow = sw128((uint32_t)((wn * 16 + (lid & 15)) * 128) + kb);
                    uint32_t a[4], bh[4], bl[4];
                    ldsm_x4(a,  hb  + arow);
                    ldsm_x4(bh, wbh + brow);
                    ldsm_x4(bl, wbl + brow);
                    mma_f16(accL, a, bh[0], bh[2]); mma_f16(accH, a, bh[1], bh[3]);
                    mma_f16(accL, a, bl[0], bl[2]); mma_f16(accH, a, bl[1], bl[3]);
                }
            }
        }
        __syncthreads();                     // all ring reads done -> gate_s alias safe

        {
            int r0 = wm * 16 + (lid >> 2);
            int c0 = wn * 16 + (lid & 3) * 2;
            gate_s[r0 * 33 + c0]           = accL[0];
            gate_s[r0 * 33 + c0 + 1]       = accL[1];
            gate_s[(r0 + 8) * 33 + c0]     = accL[2];
            gate_s[(r0 + 8) * 33 + c0 + 1] = accL[3];
            gate_s[r0 * 33 + c0 + 8]       = accH[0];
            gate_s[r0 * 33 + c0 + 9]       = accH[1];
            gate_s[(r0 + 8) * 33 + c0 + 8] = accH[2];
            gate_s[(r0 + 8) * 33 + c0 + 9] = accH[3];
        }
        __syncthreads();

#pragma unroll
        for (int u = 0; u < 2; u++) {
            int p = tid + u * 256;
            int b = p & 63, jj = p >> 6;
            const float* Prow = P + (size_t)tok_s[b] * G4H + bid * 32;
            float gi = gate_s[b * 33 + jj]      + __ldg(&Prow[jj]);
            float gf = gate_s[b * 33 + 8 + jj]  + __ldg(&Prow[8 + jj]);
            float gg = gate_s[b * 33 + 16 + jj] + __ldg(&Prow[16 + jj]);
            float go = gate_s[b * 33 + 24 + jj] + __ldg(&Prow[24 + jj]);
            float c = c_s[p];
            float si = 1.f / (1.f + expf(-gi));
            float sf = 1.f / (1.f + expf(-gf));
            float so = 1.f / (1.f + expf(-go));
            float cn = sf * c + si * tanhf(gg);
            float hn = so * tanhf(cn);
            c_s[p] = cn;
            int jg = bid * 8 + jj;
            g_h16[(s + 1) & 1][b * H_ + jg] = __float2half_rn(hn);
            if (!enc) {
                __nv_bfloat16 bhi = __float2bfloat16(hn);
                __nv_bfloat16 blo = __float2bfloat16(hn - __bfloat162float(bhi));
                size_t mrow = (size_t)(t * 64 + b) * K2_LOGITS;
                A2out[mrow + jg]        = bhi;
                A2out[mrow + 1024 + jg] = blo;
                A2out[mrow + 2048 + jg] = bhi;
            }
        }
        GSYNC();
    }
#undef GSYNC
}

// ---------------- launch ------------------------------------------------------------
extern "C" void kernel_launch(void* const* d_in, const int* in_sizes, int n_in,
                              void* d_out, int out_size)
{
    (void)in_sizes; (void)n_in; (void)out_size;
    const int*   seqs    = (const int*)  d_in[1];
    const float* enc_emb = (const float*)d_in[2];
    const float* enc_Wih = (const float*)d_in[3];
    const float* enc_Whh = (const float*)d_in[4];
    const float* enc_b   = (const float*)d_in[5];
    const float* dec_emb = (const float*)d_in[6];
    const float* dec_Wih = (const float*)d_in[7];
    const float* dec_Whh = (const float*)d_in[8];
    const float* dec_b   = (const float*)d_in[9];
    const float* out_W   = (const float*)d_in[10];
    const float* out_b   = (const float*)d_in[11];
    float* out = (float*)d_out;

    float *Penc, *Pdec, *biasr;
    __nv_bfloat16 *A2, *B2;
    __half *W16e, *W16d;
    cudaGetSymbolAddress((void**)&Penc, g_P_enc);
    cudaGetSymbolAddress((void**)&Pdec, g_P_dec);
    cudaGetSymbolAddress((void**)&A2,   g_A2);
    cudaGetSymbolAddress((void**)&B2,   g_B2);
    cudaGetSymbolAddress((void**)&W16e, g_W16_e);
    cudaGetSymbolAddress((void**)&W16d, g_W16_d);
    cudaGetSymbolAddress((void**)&biasr, g_bias_r);

    cudaFuncSetAttribute(mma_nt<0>, cudaFuncAttributeMaxDynamicSharedMemorySize, GEMM_SMEM);
    cudaFuncSetAttribute(mma_nt<1>, cudaFuncAttributeMaxDynamicSharedMemorySize, GEMM_SMEM);
    cudaFuncSetAttribute(lstm_rec_mma, cudaFuncAttributeMaxDynamicSharedMemorySize, REC_SMEM);

    // encoder vocab table: P_enc = enc_emb @ enc_Wih'(reordered)^T + b'  [8000,4096]
    split_rows<1, 0><<<(MPAD_TAB * E_ + 255) / 256, 256>>>(enc_emb, A2, V_, MPAD_TAB, E_);
    split_rows<0, 1><<<(G4H * E_ + 255) / 256, 256>>>(enc_Wih, B2, G4H, G4H, E_);
    reorder_bias<<<16, 256>>>(enc_b, biasr);
    mma_nt<0><<<dim3(G4H / 128, MPAD_TAB / 128), 256, GEMM_SMEM>>>(
        A2, B2, biasr, Penc, V_, G4H, K2_TAB, G4H);

    // decoder vocab table
    split_rows<1, 0><<<(MPAD_TAB * E_ + 255) / 256, 256>>>(dec_emb, A2, V_, MPAD_TAB, E_);
    split_rows<0, 1><<<(G4H * E_ + 255) / 256, 256>>>(dec_Wih, B2, G4H, G4H, E_);
    reorder_bias<<<16, 256>>>(dec_b, biasr);
    mma_nt<0><<<dim3(G4H / 128, MPAD_TAB / 128), 256, GEMM_SMEM>>>(
        A2, B2, biasr, Pdec, V_, G4H, K2_TAB, G4H);

    // recurrence weights (reordered, fp16 [hi|lo]); logits B operand; clear A2
    split2h_reord<<<(G4H * H_ + 255) / 256, 256>>>(enc_Whh, W16e, H_);
    split2h_reord<<<(G4H * H_ + 255) / 256, 256>>>(dec_Whh, W16d, H_);
    split_rows<0, 0><<<(NPAD_LOGITS * H_ + 255) / 256, 256>>>(out_W, B2, V_, NPAD_LOGITS, H_);
    {
        size_t n16 = ((size_t)MPAD_LOGITS * K2_LOGITS * 2) / 16;
        zero_buf<<<(unsigned)((n16 + 255) / 256), 256>>>((float4*)A2, n16);
    }

    // serial recurrence (persistent grid; decoder h written directly into A2 split form)
    lstm_rec_mma<<<NBLK, 256, REC_SMEM>>>(seqs, W16e, W16d, A2);

    // logits = Hdec_split @ out_W_split^T + out_b -> [B, 255, V]
    mma_nt<1><<<dim3(NPAD_LOGITS / 128, MPAD_LOGITS / 128), 256, GEMM_SMEM>>>(
        A2, B2, out_b, out, TDEC * B_, V_, K2_LOGITS, V_);
}

// round 14
// speedup vs baseline: 8.3658x; 1.2491x over previous
#include <cuda_runtime.h>
#include <cuda_bf16.h>
#include <cuda_fp16.h>
#include <math.h>
#include <stdint.h>

// Seq2seq LSTM forward, sm_103a. All GEMMs in 2-term fp16:
//   C = A16 @ (B16hi + B16lo)^T,  B stored [N, 2K] as [hi|lo]
//   (1) vocab tables P = embed16 @ Wih16'(2-term)^T + b'
//   (2) persistent-grid recurrence: h fp16, W fp16 [hi|lo], 2 MMA terms
//   (3) logits = Hdec16 @ outW16(2-term)^T + out_b
#define NBLK 128
#define B_   64
#define T_   256
#define V_   8000
#define E_   512
#define H_   1024
#define G4H  4096
#define TDEC 255
#define START_TOK 1

#define MPAD_LOGITS 16384
#define NPAD_LOGITS 8192
#define MPAD_TAB    8064

#define GEMM_SMEM   98304           // 2 stages x (A 16KB + Bhi 16KB + Blo 16KB)
// recurrence smem: W16 [hi|lo] 131072 | h ring 3x16384 | c 2048 | tok 256
#define RW_OFF      0
#define RH_OFF      131072
#define RC_OFF      180224
#define RT_OFF      182272
#define REC_SMEM    182528

// ---------------- PTX helpers -------------------------------------------------------
__device__ __forceinline__ uint32_t smem_u32(const void* p) {
    uint32_t a;
    asm("{ .reg .u64 t; cvta.to.shared.u64 t, %1; cvt.u32.u64 %0, t; }" : "=r"(a) : "l"(p));
    return a;
}
__device__ __forceinline__ uint32_t sw128(uint32_t off) {
    return off ^ ((off >> 3) & 0x70);
}
__device__ __forceinline__ void cp_async16(uint32_t dst, const void* src) {
    asm volatile("cp.async.cg.shared.global [%0], [%1], 16;" :: "r"(dst), "l"(src) : "memory");
}
#define CP_COMMIT() asm volatile("cp.async.commit_group;" ::: "memory")
template<int N> __device__ __forceinline__ void cp_wait() {
    asm volatile("cp.async.wait_group %0;" :: "n"(N) : "memory");
}
__device__ __forceinline__ void ldsm_x4(uint32_t r[4], uint32_t addr) {
    asm volatile("ldmatrix.sync.aligned.m8n8.x4.shared.b16 {%0,%1,%2,%3}, [%4];"
                 : "=r"(r[0]), "=r"(r[1]), "=r"(r[2]), "=r"(r[3]) : "r"(addr));
}
__device__ __forceinline__ void mma_f16(float d[4], const uint32_t a[4],
                                        uint32_t b0, uint32_t b1) {
    asm volatile(
        "mma.sync.aligned.m16n8k16.row.col.f32.f16.f16.f32 "
        "{%0,%1,%2,%3}, {%4,%5,%6,%7}, {%8,%9}, {%0,%1,%2,%3};"
        : "+f"(d[0]), "+f"(d[1]), "+f"(d[2]), "+f"(d[3])
        : "r"(a[0]), "r"(a[1]), "r"(a[2]), "r"(a[3]), "r"(b0), "r"(b1));
}

// ---------------- device scratch (allocation-free rule) -----------------------------
__device__ float g_P_enc[(size_t)V_ * G4H];
__device__ float g_P_dec[(size_t)V_ * G4H];
__device__ __half g_A16[(size_t)MPAD_LOGITS * H_];    // GEMM A operand (reused)
__device__ __half g_B16[(size_t)NPAD_LOGITS * 2 * H_]; // GEMM B operand [hi|lo] (reused)
__device__ __half g_W16_e[(size_t)G4H * 2048];        // recurrence W, reordered [hi|lo]
__device__ __half g_W16_d[(size_t)G4H * 2048];
__device__ __half g_h16[2][B_ * H_];                  // double-buffered fp16 h
__device__ float g_bias_r[G4H];
__device__ unsigned g_arrive = 0;
__device__ unsigned g_phase  = 0;

// ---------------- conversion helpers ------------------------------------------------
// plain fp16 cast with optional gate-row reorder and zero padding
template<int REORD>
__global__ void to_f16(const float* __restrict__ X, __half* __restrict__ Y,
                       int M_in, int M_pad, int K)
{
    int idx = blockIdx.x * blockDim.x + threadIdx.x;
    if (idx >= M_pad * K) return;
    int m = idx / K, k = idx - m * K;
    int src = m;
    if (REORD) {
        int blk = m >> 5, r = m & 31;
        src = (r >> 3) * H_ + blk * 8 + (r & 7);
    }
    float x = (src < M_in) ? X[(size_t)src * K + k] : 0.f;
    Y[(size_t)m * K + k] = __float2half_rn(x);
}

// fp16 two-term split [hi | lo] with optional reorder and zero padding
template<int REORD>
__global__ void split2_f16(const float* __restrict__ X, __half* __restrict__ Y,
                           int M_in, int M_pad, int K)
{
    int idx = blockIdx.x * blockDim.x + threadIdx.x;
    if (idx >= M_pad * K) return;
    int m = idx / K, k = idx - m * K;
    int src = m;
    if (REORD) {
        int blk = m >> 5, r = m & 31;
        src = (r >> 3) * H_ + blk * 8 + (r & 7);
    }
    float x = (src < M_in) ? X[(size_t)src * K + k] : 0.f;
    __half hi = __float2half_rn(x);
    __half lo = __float2half_rn(x - __half2float(hi));
    size_t rb = (size_t)m * (2 * K);
    Y[rb + k]     = hi;
    Y[rb + K + k] = lo;
}

__global__ void reorder_bias(const float* __restrict__ b, float* __restrict__ br) {
    int m = blockIdx.x * blockDim.x + threadIdx.x;
    if (m >= G4H) return;
    int blk = m >> 5, r = m & 31;
    br[m] = b[(r >> 3) * H_ + blk * 8 + (r & 7)];
}

__global__ void zero_buf(float4* p, size_t n16) {
    size_t i = (size_t)blockIdx.x * blockDim.x + threadIdx.x;
    if (i < n16) p[i] = make_float4(0.f, 0.f, 0.f, 0.f);
}

// ---------------- 2-term fp16 HMMA GEMM ---------------------------------------------
// C[M,N] = A16[M,K] @ (B16hi + B16lo)[N,K]^T + bias;  B16 stored [N, 2K] = [hi|lo].
// 128x128 tiles, 64-col chunks (128B sw128 rows), 2-stage ring, 2 CTAs/SM.
// MODE 0: row-major C.  MODE 1: logits remap m=t*64+b -> C[(b*255+t)*ldC + n]
template<int MODE>
__global__ void __launch_bounds__(256, 2) mma_nt2(
    const __half* __restrict__ A16, const __half* __restrict__ B16,
    const float* __restrict__ bias, float* __restrict__ C,
    int M_eff, int N_eff, int K, int ldC)
{
    extern __shared__ __align__(1024) char dsm[];
    const uint32_t sb = smem_u32(dsm);
    const int tid = threadIdx.x;
    const int wid = tid >> 5, lid = tid & 31;
    const int wm = wid & 3, wn = wid >> 2;
    const int bm = blockIdx.y * 128, bn = blockIdx.x * 128;
    const int nch = K / 64;

    auto loadT = [&](int ch) {
        uint32_t stg = sb + (ch & 1) * 49152;
#pragma unroll
        for (int j = 0; j < 4; j++) {
            int i = tid + j * 256;
            int r = i >> 3, cb = (i & 7) * 16;
            uint32_t off = sw128((uint32_t)(r * 128 + cb));
            cp_async16(stg + off,
                       (const char*)A16 + ((size_t)(bm + r) * K + ch * 64) * 2 + cb);
            cp_async16(stg + 16384 + off,
                       (const char*)B16 + ((size_t)(bn + r) * 2 * K + ch * 64) * 2 + cb);
            cp_async16(stg + 32768 + off,
                       (const char*)B16 + ((size_t)(bn + r) * 2 * K + K + ch * 64) * 2 + cb);
        }
        CP_COMMIT();
    };

    float acc[2][8][4];
#pragma unroll
    for (int i = 0; i < 2; i++)
#pragma unroll
        for (int j = 0; j < 8; j++)
#pragma unroll
            for (int q = 0; q < 4; q++) acc[i][j][q] = 0.f;

    loadT(0);
    for (int i = 0; i < nch; i++) {
        if (i + 1 < nch) { loadT(i + 1); cp_wait<1>(); }
        else             { cp_wait<0>(); }
        __syncthreads();
        const uint32_t ab  = sb + (i & 1) * 49152;
        const uint32_t bhb = ab + 16384;
        const uint32_t blb = ab + 32768;
#pragma unroll
        for (int ks = 0; ks < 4; ks++) {
            const uint32_t kb = (uint32_t)((ks * 16 + ((lid >> 4) << 3)) * 2);
            uint32_t a[2][4], b[4][4];
#pragma unroll
            for (int mi = 0; mi < 2; mi++)
                ldsm_x4(a[mi], ab + sw128((uint32_t)((wm * 32 + mi * 16 + (lid & 15)) * 128) + kb));
            // hi term
#pragma unroll
            for (int ni = 0; ni < 4; ni++)
                ldsm_x4(b[ni], bhb + sw128((uint32_t)((wn * 64 + ni * 16 + (lid & 15)) * 128) + kb));
#pragma unroll
            for (int mi = 0; mi < 2; mi++)
#pragma unroll
                for (int ni = 0; ni < 4; ni++) {
                    mma_f16(acc[mi][2 * ni + 0], a[mi], b[ni][0], b[ni][2]);
                    mma_f16(acc[mi][2 * ni + 1], a[mi], b[ni][1], b[ni][3]);
                }
            // lo term (reuse b regs)
#pragma unroll
            for (int ni = 0; ni < 4; ni++)
                ldsm_x4(b[ni], blb + sw128((uint32_t)((wn * 64 + ni * 16 + (lid & 15)) * 128) + kb));
#pragma unroll
            for (int mi = 0; mi < 2; mi++)
#pragma unroll
                for (int ni = 0; ni < 4; ni++) {
                    mma_f16(acc[mi][2 * ni + 0], a[mi], b[ni][0], b[ni][2]);
                    mma_f16(acc[mi][2 * ni + 1], a[mi], b[ni][1], b[ni][3]);
                }
        }
        __syncthreads();   // stage consumed before next-next load overwrites it
    }

#pragma unroll
    for (int mi = 0; mi < 2; mi++) {
        int m0 = bm + wm * 32 + mi * 16 + (lid >> 2);
#pragma unroll
        for (int half = 0; half < 2; half++) {
            int m = m0 + half * 8;
            if (m >= M_eff) continue;
            size_t obase;
            if (MODE == 0) obase = (size_t)m * ldC;
            else {
                int t = m >> 6, b = m & 63;
                obase = ((size_t)b * TDEC + t) * ldC;
            }
#pragma unroll
            for (int nj = 0; nj < 8; nj++) {
                int n = bn + wn * 64 + nj * 8 + (lid & 3) * 2;
                float v0 = acc[mi][nj][half * 2 + 0];
                float v1 = acc[mi][nj][half * 2 + 1];
                if (n < N_eff)     C[obase + n]     = v0 + __ldg(&bias[n]);
                if (n + 1 < N_eff) C[obase + n + 1] = v1 + __ldg(&bias[n + 1]);
            }
        }
    }
}

// ---------------- persistent HMMA LSTM recurrence (fp16 h, 2-term W) ----------------
// 128 blocks x 256 thr; block owns 32 reordered gate rows (4 gates x 8 hidden units).
// W16' = [hi|lo] (32 x 2048 fp16) resident in smem across all 511 steps.
// 8 k-chunks of 128 cols/step; per chunk: gates += h16*W16hi + h16*W16lo (fp32 accum).
__global__ void __launch_bounds__(256, 1) lstm_rec_mma(
    const int* __restrict__ seqs,
    const __half* __restrict__ W16_e,
    const __half* __restrict__ W16_d,
    __half* __restrict__ Hdec16)
{
    extern __shared__ __align__(1024) char dsm[];
    const uint32_t sb = smem_u32(dsm);
    float* gate_s = (float*)(dsm + RH_OFF);      // [64][33], aliases h-ring stage 0
    float* c_s    = (float*)(dsm + RC_OFF);      // [512]: p = jj*64 + b
    int*   tok_s  = (int*)  (dsm + RT_OFF);

    const int tid = threadIdx.x;
    const int bid = blockIdx.x;
    const int wid = tid >> 5, lid = tid & 31;
    const int wm = wid & 3, wn = wid >> 2;

    unsigned base = 0;
    if (tid == 0) base = atomicAdd(&g_phase, 0u);   // replay-safe phase baseline
    unsigned tgt = 0;

    for (int i = bid * 256 + tid; i < B_ * H_; i += NBLK * 256)
        g_h16[0][i] = __float2half_rn(0.f);
    c_s[tid] = 0.f; c_s[tid + 256] = 0.f;

    auto loadW = [&](const __half* Wsrc) {
#pragma unroll
        for (int j = 0; j < 32; j++) {
            int i = tid + j * 256;
            int row = i >> 8;
            int cb  = (i & 255) * 16;
            int ci  = cb >> 7, inner = cb & 127;
            cp_async16(sb + RW_OFF + ci * 4096 + sw128((uint32_t)(row * 128 + inner)),
                       (const char*)Wsrc + (size_t)(bid * 32 + row) * 4096 + cb);
        }
        CP_COMMIT();
    };
    loadW(W16_e);   // drained by the first chunk-loop wait

#define GSYNC() do {                                                     \
    __syncthreads();                                                     \
    if (tid == 0) {                                                      \
        ++tgt;                                                           \
        __threadfence();                                                 \
        unsigned prev_ = atomicAdd(&g_arrive, 1u);                       \
        if (prev_ == NBLK - 1) {                                         \
            atomicExch(&g_arrive, 0u);                                   \
            __threadfence();                                             \
            atomicAdd(&g_phase, 1u);                                     \
        } else {                                                         \
            volatile unsigned* vp_ = &g_phase;                           \
            while ((unsigned)(*vp_ - base) < tgt)                        \
                __nanosleep(32);                                         \
            __threadfence();                                             \
        }                                                                \
    }                                                                    \
    __syncthreads();                                                     \
} while (0)

    GSYNC();   // h0 visible grid-wide

    for (int s = 0; s < T_ + TDEC; s++) {
        const bool enc = (s < T_);
        const int t = enc ? s : s - T_;
        const float* __restrict__ P = enc ? g_P_enc : g_P_dec;
        const __half* __restrict__ h16 = g_h16[s & 1];

        if (s == T_) loadW(W16_d);           // decoder weights; drained at chunk-0 wait
        if (tid < B_)
            tok_s[tid] = enc ? seqs[tid * T_ + t]
                             : (t == 0 ? START_TOK : seqs[tid * T_ + t]);

        // h chunk loader: 128 fp16 cols = two 64-col sw128 tiles (8KB each)
        auto loadH = [&](int ch) {
            uint32_t stg = sb + RH_OFF + (ch % 3) * 16384;
#pragma unroll
            for (int j = 0; j < 4; j++) {
                int i = tid + j * 256;       // 0..1023
                int r = i >> 4;              // batch row 0..63
                int seg = i & 15;
                int half = seg >> 3, cb = (seg & 7) * 16;
                uint32_t off = sw128((uint32_t)(r * 128 + cb));
                cp_async16(stg + half * 8192 + off,
                           (const char*)h16 + (size_t)r * 2048 + ch * 256 + half * 128 + cb);
            }
            CP_COMMIT();
        };

        float accL[4] = {0.f, 0.f, 0.f, 0.f};
        float accH[4] = {0.f, 0.f, 0.f, 0.f};
        loadH(0); loadH(1);

        for (int ch = 0; ch < 8; ch++) {
            if (ch < 7) cp_wait<1>(); else cp_wait<0>();
            __syncthreads();
            if (ch + 2 < 8) loadH(ch + 2);   // targets stage (ch-1)%3, vacated pre-sync
            const uint32_t hstage = sb + RH_OFF + (ch % 3) * 16384;
#pragma unroll
            for (int half = 0; half < 2; half++) {
                const uint32_t hb  = hstage + half * 8192;
                const uint32_t wbh = sb + RW_OFF + (2 * ch + half) * 4096;
                const uint32_t wbl = sb + RW_OFF + (16 + 2 * ch + half) * 4096;
#pragma unroll
                for (int ks = 0; ks < 4; ks++) {
                    const uint32_t kb = (uint32_t)((ks * 16 + ((lid >> 4) << 3)) * 2);
                    const uint32_t arow = sw128((uint32_t)((wm * 16 + (lid & 15)) * 128) + kb);
                    const uint32_t brow = sw128((uint32_t)((wn * 16 + (lid & 15)) * 128) + kb);
                    uint32_t a[4], bh[4], bl[4];
                    ldsm_x4(a,  hb  + arow);
                    ldsm_x4(bh, wbh + brow);
                    ldsm_x4(bl, wbl + brow);
                    mma_f16(accL, a, bh[0], bh[2]); mma_f16(accH, a, bh[1], bh[3]);
                    mma_f16(accL, a, bl[0], bl[2]); mma_f16(accH, a, bl[1], bl[3]);
                }
            }
        }
        __syncthreads();                     // all ring reads done -> gate_s alias safe

        {
            int r0 = wm * 16 + (lid >> 2);
            int c0 = wn * 16 + (lid & 3) * 2;
            gate_s[r0 * 33 + c0]           = accL[0];
            gate_s[r0 * 33 + c0 + 1]       = accL[1];
            gate_s[(r0 + 8) * 33 + c0]     = accL[2];
            gate_s[(r0 + 8) * 33 + c0 + 1] = accL[3];
            gate_s[r0 * 33 + c0 + 8]       = accH[0];
            gate_s[r0 * 33 + c0 + 9]       = accH[1];
            gate_s[(r0 + 8) * 33 + c0 + 8] = accH[2];
            gate_s[(r0 + 8) * 33 + c0 + 9] = accH[3];
        }
        __syncthreads();

#pragma unroll
        for (int u = 0; u < 2; u++) {
            int p = tid + u * 256;
            int b = p & 63, jj = p >> 6;
            const float* Prow = P + (size_t)tok_s[b] * G4H + bid * 32;
            float gi = gate_s[b * 33 + jj]      + __ldg(&Prow[jj]);
            float gf = gate_s[b * 33 + 8 + jj]  + __ldg(&Prow[8 + jj]);
            float gg = gate_s[b * 33 + 16 + jj] + __ldg(&Prow[16 + jj]);
            float go = gate_s[b * 33 + 24 + jj] + __ldg(&Prow[24 + jj]);
            float c = c_s[p];
            float si = 1.f / (1.f + expf(-gi));
            float sf = 1.f / (1.f + expf(-gf));
            float so = 1.f / (1.f + expf(-go));
            float cn = sf * c + si * tanhf(gg);
            float hn = so * tanhf(cn);
            c_s[p] = cn;
            int jg = bid * 8 + jj;
            __half h16v = __float2half_rn(hn);
            g_h16[(s + 1) & 1][b * H_ + jg] = h16v;
            if (!enc)
                Hdec16[(size_t)(t * 64 + b) * H_ + jg] = h16v;
        }
        GSYNC();
    }
#undef GSYNC
}

// ---------------- launch ------------------------------------------------------------
extern "C" void kernel_launch(void* const* d_in, const int* in_sizes, int n_in,
                              void* d_out, int out_size)
{
    (void)in_sizes; (void)n_in; (void)out_size;
    const int*   seqs    = (const int*)  d_in[1];
    const float* enc_emb = (const float*)d_in[2];
    const float* enc_Wih = (const float*)d_in[3];
    const float* enc_Whh = (const float*)d_in[4];
    const float* enc_b   = (const float*)d_in[5];
    const float* dec_emb = (const float*)d_in[6];
    const float* dec_Wih = (const float*)d_in[7];
    const float* dec_Whh = (const float*)d_in[8];
    const float* dec_b   = (const float*)d_in[9];
    const float* out_W   = (const float*)d_in[10];
    const float* out_b   = (const float*)d_in[11];
    float* out = (float*)d_out;

    float *Penc, *Pdec, *biasr;
    __half *A16, *B16, *W16e, *W16d;
    cudaGetSymbolAddress((void**)&Penc, g_P_enc);
    cudaGetSymbolAddress((void**)&Pdec, g_P_dec);
    cudaGetSymbolAddress((void**)&A16,  g_A16);
    cudaGetSymbolAddress((void**)&B16,  g_B16);
    cudaGetSymbolAddress((void**)&W16e, g_W16_e);
    cudaGetSymbolAddress((void**)&W16d, g_W16_d);
    cudaGetSymbolAddress((void**)&biasr, g_bias_r);

    cudaFuncSetAttribute(mma_nt2<0>, cudaFuncAttributeMaxDynamicSharedMemorySize, GEMM_SMEM);
    cudaFuncSetAttribute(mma_nt2<1>, cudaFuncAttributeMaxDynamicSharedMemorySize, GEMM_SMEM);
    cudaFuncSetAttribute(lstm_rec_mma, cudaFuncAttributeMaxDynamicSharedMemorySize, REC_SMEM);

    // encoder vocab table: P_enc = enc_emb16 @ enc_Wih'(2-term)^T + b'  [8000,4096]
    to_f16<0><<<(MPAD_TAB * E_ + 255) / 256, 256>>>(enc_emb, A16, V_, MPAD_TAB, E_);
    split2_f16<1><<<(G4H * E_ + 255) / 256, 256>>>(enc_Wih, B16, G4H, G4H, E_);
    reorder_bias<<<16, 256>>>(enc_b, biasr);
    mma_nt2<0><<<dim3(G4H / 128, MPAD_TAB / 128), 256, GEMM_SMEM>>>(
        A16, B16, biasr, Penc, V_, G4H, E_, G4H);

    // decoder vocab table
    to_f16<0><<<(MPAD_TAB * E_ + 255) / 256, 256>>>(dec_emb, A16, V_, MPAD_TAB, E_);
    split2_f16<1><<<(G4H * E_ + 255) / 256, 256>>>(dec_Wih, B16, G4H, G4H, E_);
    reorder_bias<<<16, 256>>>(dec_b, biasr);
    mma_nt2<0><<<dim3(G4H / 128, MPAD_TAB / 128), 256, GEMM_SMEM>>>(
        A16, B16, biasr, Pdec, V_, G4H, E_, G4H);

    // recurrence weights (reordered, fp16 [hi|lo]); logits B operand; zero A16 pad tail
    split2_f16<1><<<(G4H * H_ + 255) / 256, 256>>>(enc_Whh, W16e, G4H, G4H, H_);
    split2_f16<1><<<(G4H * H_ + 255) / 256, 256>>>(dec_Whh, W16d, G4H, G4H, H_);
    split2_f16<0><<<(NPAD_LOGITS * H_ + 255) / 256, 256>>>(out_W, B16, V_, NPAD_LOGITS, H_);
    zero_buf<<<32, 256>>>((float4*)(A16 + (size_t)(TDEC * B_) * H_),
                          ((size_t)(MPAD_LOGITS - TDEC * B_) * H_ * 2) / 16);

    // serial recurrence (persistent grid; decoder h written directly into A16)
    lstm_rec_mma<<<NBLK, 256, REC_SMEM>>>(seqs, W16e, W16d, A16);

    // logits = Hdec16 @ outW16(2-term)^T + out_b -> [B, 255, V]
    mma_nt2<1><<<dim3(NPAD_LOGITS / 128, MPAD_LOGITS / 128), 256, GEMM_SMEM>>>(
        A16, B16, out_b, out, TDEC * B_, V_, H_, V_);
}